// round 9
// baseline (speedup 1.0000x reference)
#include <cuda_runtime.h>
#include <cuda_bf16.h>
#include <cstdint>

// Problem constants
#define BB 8
#define LL 2048
#define DD 512
#define RR 512
#define M1 (BB * LL)   // 16384 flattened (B,L)

typedef __nv_bfloat16 bf16;
typedef __nv_bfloat162 bf162;

__device__ __forceinline__ uint32_t smem_to_u32(const void* smem_ptr) {
    uint32_t addr;
    asm("{ .reg .u64 tmp; cvta.to.shared.u64 tmp, %1; cvt.u32.u64 %0, tmp; }"
        : "=r"(addr) : "l"(smem_ptr));
    return addr;
}

__device__ __forceinline__ void bf16split(float x, bf16& h, bf16& l) {
    h = __float2bfloat16(x);
    l = __float2bfloat16(x - __bfloat162float(h));
}

#define CPASYNC16(dst, src) \
    asm volatile("cp.async.cg.shared.global [%0], [%1], 16;" :: "r"(dst), "l"(src))
#define CPASYNC_COMMIT() asm volatile("cp.async.commit_group;" ::: "memory")

#define LDSM4(r0, r1, r2, r3, addr) \
    asm volatile("ldmatrix.sync.aligned.m8n8.x4.shared.b16 {%0,%1,%2,%3}, [%4];" \
                 : "=r"(r0), "=r"(r1), "=r"(r2), "=r"(r3) : "r"(addr))

#define MMA16816(c, a, b) \
    asm volatile("mma.sync.aligned.m16n8k16.row.col.f32.bf16.bf16.f32 " \
                 "{%0,%1,%2,%3}, {%4,%5,%6,%7}, {%8,%9}, {%0,%1,%2,%3};" \
                 : "+f"((c)[0]), "+f"((c)[1]), "+f"((c)[2]), "+f"((c)[3]) \
                 : "r"((a)[0]), "r"((a)[1]), "r"((a)[2]), "r"((a)[3]), \
                   "r"((b)[0]), "r"((b)[1]))

// ---------------- scratch (device globals; no allocation allowed) ----------
__device__ bf16  g_query_h[(size_t)M1 * DD];
__device__ bf16  g_query_l[(size_t)M1 * DD];
__device__ bf16  g_wq_h[DD * DD];
__device__ bf16  g_wq_l[DD * DD];
__device__ bf16  g_wc_h[RR * LL];
__device__ bf16  g_wc_l[RR * LL];
__device__ bf16  g_qT_h[(size_t)BB * DD * LL];
__device__ bf16  g_qT_l[(size_t)BB * DD * LL];
__device__ bf16  g_qcat_h[(size_t)M1 * 1024];   // [q^2 | q]
__device__ bf16  g_qcat_l[(size_t)M1 * 1024];
__device__ bf16  g_bcat_h[RR * 1024];           // [invw2 | -2c*invw2]
__device__ bf16  g_bcat_l[RR * 1024];
__device__ float g_z[(size_t)M1 * RR];
__device__ bf16  g_fss_h[(size_t)M1 * RR];
__device__ bf16  g_fss_l[(size_t)M1 * RR];
__device__ bf16  g_conqT_h[(size_t)BB * DD * RR];
__device__ bf16  g_conqT_l[(size_t)BB * DD * RR];
__device__ float g_cc[RR];

// ---------------------------------------------------------------------------
// split: fp32 -> (hi, lo) bf16 (for Wq, Wc)
// ---------------------------------------------------------------------------
__global__ void split_kernel(const float* __restrict__ src, bf16* __restrict__ hi,
                             bf16* __restrict__ lo, int n4) {
    int i = blockIdx.x * blockDim.x + threadIdx.x;
    if (i >= n4) return;
    float4 v = ((const float4*)src)[i];
    bf16 h0, l0, h1, l1, h2, l2, h3, l3;
    bf16split(v.x, h0, l0); bf16split(v.y, h1, l1);
    bf16split(v.z, h2, l2); bf16split(v.w, h3, l3);
    bf162 hh0; hh0.x = h0; hh0.y = h1;
    bf162 hh1; hh1.x = h2; hh1.y = h3;
    bf162 ll0; ll0.x = l0; ll0.y = l1;
    bf162 ll1; ll1.x = l2; ll1.y = l3;
    ((bf162*)hi)[i * 2 + 0] = hh0;
    ((bf162*)hi)[i * 2 + 1] = hh1;
    ((bf162*)lo)[i * 2 + 0] = ll0;
    ((bf162*)lo)[i * 2 + 1] = ll1;
}

// ---------------------------------------------------------------------------
// query prep: single read of query -> row-major split AND transposed split
// ---------------------------------------------------------------------------
__global__ void query_prep_kernel(const float* __restrict__ query) {
    __shared__ float tile[32][33];
    int b = blockIdx.z;
    int l0 = blockIdx.x * 32, d0 = blockIdx.y * 32;
    int tx = threadIdx.x, ty = threadIdx.y;
    const float* src = query + (size_t)b * LL * DD;
#pragma unroll
    for (int i = 0; i < 4; i++) {
        int l = l0 + ty + 8 * i;
        float v = src[(size_t)l * DD + d0 + tx];
        tile[ty + 8 * i][tx] = v;
        bf16 h, lw;
        bf16split(v, h, lw);
        size_t idx = (size_t)(b * LL + l) * DD + d0 + tx;
        g_query_h[idx] = h;
        g_query_l[idx] = lw;
    }
    __syncthreads();
    size_t base = (size_t)b * DD * LL;
#pragma unroll
    for (int i = 0; i < 4; i++) {
        float v = tile[tx][ty + 8 * i];
        bf16 h, lw;
        bf16split(v, h, lw);
        size_t idx = base + (size_t)(d0 + ty + 8 * i) * LL + l0 + tx;
        g_qT_h[idx] = h;
        g_qT_l[idx] = lw;
    }
}

// ---------------------------------------------------------------------------
// prep: bcat = [invw2 | -2c*invw2] split, cc[r] = sum c^2*invw2
// ---------------------------------------------------------------------------
__global__ void prep_kernel(const float* __restrict__ centers,
                            const float* __restrict__ widths) {
    int r = blockIdx.x;
    int t = threadIdx.x;  // 128
    float acc = 0.f;
    for (int d = t; d < DD; d += 128) {
        float w = widths[r * DD + d];
        float c = centers[r * DD + d];
        float iw = 1.0f / (w * w);
        float b2 = -2.0f * c * iw;
        bf16 h, l;
        bf16split(iw, h, l);
        g_bcat_h[r * 1024 + d] = h;
        g_bcat_l[r * 1024 + d] = l;
        bf16split(b2, h, l);
        g_bcat_h[r * 1024 + 512 + d] = h;
        g_bcat_l[r * 1024 + 512 + d] = l;
        acc += c * c * iw;
    }
    __shared__ float sred[128];
    sred[t] = acc;
    __syncthreads();
    for (int s = 64; s > 0; s >>= 1) {
        if (t < s) sred[t] += sred[t + s];
        __syncthreads();
    }
    if (t == 0) g_cc[r] = sred[0];
}

// ---------------------------------------------------------------------------
// bf16-split NT GEMM via mma.sync m16n8k16, 3 passes (AhBh + AhBl + AlBh).
// 128x128 CTA tile, 8 warps of 64x32. K-chunk 64, 3-stage cp.async pipeline,
// single __syncthreads per chunk (wait -> sync -> issue kt+2 -> compute kt).
// SMEM tile: 128 rows x 128B data, 144B pitch (conflict-free ldmatrix+store).
// MODE 0: qcat ((v+aux)^2 | (v+aux), split; ldc=1024)
// MODE 1: fp32 scale*(v+aux[n]) -> Cf
// MODE 2: split bf16 v+aux[n]   -> Ch/Cl
// MODE 3: fp32 raw              -> Cf
// ---------------------------------------------------------------------------
#define TPITCH 144
#define TILE_B (128 * TPITCH)        // 18432
#define STAGE_B (4 * TILE_B)         // 73728: Ah, Al, Bh, Bl
#define GEMM_SMEM (3 * STAGE_B)      // 221184 <= 227KB cap

template <int MODE>
__global__ __launch_bounds__(256, 1) void gemm_bf16s(
    const bf16* __restrict__ Ah, const bf16* __restrict__ Al, int lda, size_t sA,
    const bf16* __restrict__ Bh, const bf16* __restrict__ Bl, int ldb, size_t sB,
    float* __restrict__ Cf, bf16* __restrict__ Ch, bf16* __restrict__ Cl,
    int ldc, size_t sC, const float* __restrict__ aux, int K) {
    extern __shared__ char smem[];
    uint32_t sb = smem_to_u32(smem);
    int t = threadIdx.x;
    int lane = t & 31, wid = t >> 5;
    int wm = wid & 1, wn = wid >> 1;
    int bn = blockIdx.x * 128, bm = blockIdx.y * 128;
    size_t bz = blockIdx.z;
    Ah += bz * sA; Al += bz * sA;
    Bh += bz * sB; Bl += bz * sB;

    // cp.async plan: each thread does 16 x 16B per 64-wide K-chunk.
    int r0 = t >> 3;
    int cc = t & 7;
    const bf16* gA_h = Ah + (size_t)(bm + r0) * lda + cc * 8;
    const bf16* gA_l = Al + (size_t)(bm + r0) * lda + cc * 8;
    const bf16* gB_h = Bh + (size_t)(bn + r0) * ldb + cc * 8;
    const bf16* gB_l = Bl + (size_t)(bn + r0) * ldb + cc * 8;
    uint32_t soff = (uint32_t)(r0 * TPITCH + cc * 16);

    float acc[4][4][4] = {};
    const int nk = K >> 6;

    // prologue: chunks 0,1 -> stages 0,1
#pragma unroll
    for (int pc = 0; pc < 2; pc++) {
        uint32_t db = sb + pc * STAGE_B;
        int koff = pc * 64;
#pragma unroll
        for (int i = 0; i < 4; i++) {
            uint32_t o = soff + (uint32_t)(i * 32 * TPITCH);
            size_t ga = (size_t)(32 * i) * lda + koff;
            size_t gb = (size_t)(32 * i) * ldb + koff;
            CPASYNC16(db + o,              gA_h + ga);
            CPASYNC16(db + TILE_B + o,     gA_l + ga);
            CPASYNC16(db + 2 * TILE_B + o, gB_h + gb);
            CPASYNC16(db + 3 * TILE_B + o, gB_l + gb);
        }
        CPASYNC_COMMIT();
    }

    int lm = lane & 15, lq = lane >> 4;
    uint32_t a_base = (uint32_t)((wm * 64 + lm) * TPITCH);
    uint32_t b_base = (uint32_t)((wn * 32 + lm) * TPITCH);

    int stage = 0;      // stage index of chunk kt
    for (int kt = 0; kt < nk; kt++) {
        // complete chunk kt's loads (leave kt+1 in flight); drain all at tail
        if (kt + 1 < nk) {
            asm volatile("cp.async.wait_group 1;" ::: "memory");
        } else {
            asm volatile("cp.async.wait_group 0;" ::: "memory");
        }
        __syncthreads();   // publish stage kt to all warps; fence slot reuse

        // prefetch chunk kt+2 into the slot freed at iteration kt-1
        if (kt + 2 < nk) {
            int ps = stage + 2; if (ps >= 3) ps -= 3;
            uint32_t db = sb + ps * STAGE_B;
            int koff = (kt + 2) * 64;
#pragma unroll
            for (int i = 0; i < 4; i++) {
                uint32_t o = soff + (uint32_t)(i * 32 * TPITCH);
                size_t ga = (size_t)(32 * i) * lda + koff;
                size_t gb = (size_t)(32 * i) * ldb + koff;
                CPASYNC16(db + o,              gA_h + ga);
                CPASYNC16(db + TILE_B + o,     gA_l + ga);
                CPASYNC16(db + 2 * TILE_B + o, gB_h + gb);
                CPASYNC16(db + 3 * TILE_B + o, gB_l + gb);
            }
            CPASYNC_COMMIT();
        }

        uint32_t base = sb + stage * STAGE_B;
#pragma unroll
        for (int ks = 0; ks < 4; ks++) {
            uint32_t off16 = (uint32_t)((2 * ks + lq) * 16);
            uint32_t a[4][4], bh[4][2], bl[4][2];
#pragma unroll
            for (int i = 0; i < 4; i++)
                LDSM4(a[i][0], a[i][1], a[i][2], a[i][3],
                      base + a_base + i * (16 * TPITCH) + off16);
#pragma unroll
            for (int jj = 0; jj < 2; jj++) {
                uint32_t q0, q1, q2, q3;
                LDSM4(q0, q1, q2, q3,
                      base + 2 * TILE_B + b_base + jj * (16 * TPITCH) + off16);
                bh[2 * jj][0] = q0; bh[2 * jj][1] = q2;
                bh[2 * jj + 1][0] = q1; bh[2 * jj + 1][1] = q3;
            }
#pragma unroll
            for (int i = 0; i < 4; i++)
#pragma unroll
                for (int j = 0; j < 4; j++) MMA16816(acc[i][j], a[i], bh[j]);
#pragma unroll
            for (int jj = 0; jj < 2; jj++) {
                uint32_t q0, q1, q2, q3;
                LDSM4(q0, q1, q2, q3,
                      base + 3 * TILE_B + b_base + jj * (16 * TPITCH) + off16);
                bl[2 * jj][0] = q0; bl[2 * jj][1] = q2;
                bl[2 * jj + 1][0] = q1; bl[2 * jj + 1][1] = q3;
            }
#pragma unroll
            for (int i = 0; i < 4; i++)
#pragma unroll
                for (int j = 0; j < 4; j++) MMA16816(acc[i][j], a[i], bl[j]);
#pragma unroll
            for (int i = 0; i < 4; i++)
                LDSM4(a[i][0], a[i][1], a[i][2], a[i][3],
                      base + TILE_B + a_base + i * (16 * TPITCH) + off16);
#pragma unroll
            for (int i = 0; i < 4; i++)
#pragma unroll
                for (int j = 0; j < 4; j++) MMA16816(acc[i][j], a[i], bh[j]);
        }
        stage++; if (stage == 3) stage = 0;
    }

    // epilogue (register-direct)
    int rbase = bm + wm * 64 + (lane >> 2);
    int nbase = bn + wn * 32 + (lane & 3) * 2;
#pragma unroll
    for (int i = 0; i < 4; i++) {
#pragma unroll
        for (int j = 0; j < 4; j++) {
            int n = nbase + j * 8;
#pragma unroll
            for (int h = 0; h < 2; h++) {
                int m = rbase + i * 16 + h * 8;
                float v0 = acc[i][j][2 * h];
                float v1 = acc[i][j][2 * h + 1];
                if (MODE == 0) {
                    size_t crow = (size_t)m * ldc;
                    float q0 = v0 + aux[n], q1 = v1 + aux[n + 1];
                    bf16 h0, l0, h1, l1;
                    bf16split(q0 * q0, h0, l0); bf16split(q1 * q1, h1, l1);
                    bf162 hh; hh.x = h0; hh.y = h1;
                    bf162 ll; ll.x = l0; ll.y = l1;
                    *(bf162*)(Ch + crow + n) = hh;
                    *(bf162*)(Cl + crow + n) = ll;
                    bf16split(q0, h0, l0); bf16split(q1, h1, l1);
                    hh.x = h0; hh.y = h1; ll.x = l0; ll.y = l1;
                    *(bf162*)(Ch + crow + 512 + n) = hh;
                    *(bf162*)(Cl + crow + 512 + n) = ll;
                } else if (MODE == 1) {
                    const float scale = -0.5f / (float)DD;
                    size_t crow = (size_t)m * ldc;
                    float2 o;
                    o.x = scale * (v0 + aux[n]);
                    o.y = scale * (v1 + aux[n + 1]);
                    *(float2*)(Cf + crow + n) = o;
                } else if (MODE == 2) {
                    size_t crow = bz * sC + (size_t)m * ldc;
                    float q0 = v0 + aux[n], q1 = v1 + aux[n + 1];
                    bf16 h0, l0, h1, l1;
                    bf16split(q0, h0, l0); bf16split(q1, h1, l1);
                    bf162 hh; hh.x = h0; hh.y = h1;
                    bf162 ll; ll.x = l0; ll.y = l1;
                    *(bf162*)(Ch + crow + n) = hh;
                    *(bf162*)(Cl + crow + n) = ll;
                } else {
                    size_t crow = bz * sC + (size_t)m * ldc;
                    float2 o; o.x = v0; o.y = v1;
                    *(float2*)(Cf + crow + n) = o;
                }
            }
        }
    }
}

// ---------------------------------------------------------------------------
// softmax over R: reads fp32 g_z (scaled logits), writes split Fss
// ---------------------------------------------------------------------------
__global__ void softmax_kernel() {
    int row = blockIdx.x;
    int t = threadIdx.x;  // 256
    const float* zrow = g_z + (size_t)row * RR;
    float v0 = zrow[t];
    float v1 = zrow[t + 256];
    float m = fmaxf(v0, v1);
#pragma unroll
    for (int o = 16; o > 0; o >>= 1) m = fmaxf(m, __shfl_xor_sync(0xffffffffu, m, o));
    __shared__ float sm[8];
    __shared__ float ss[8];
    int wid = t >> 5, lid = t & 31;
    if (lid == 0) sm[wid] = m;
    __syncthreads();
    float mm = sm[0];
#pragma unroll
    for (int i = 1; i < 8; i++) mm = fmaxf(mm, sm[i]);
    float e0 = __expf(v0 - mm), e1 = __expf(v1 - mm);
    float s = e0 + e1;
#pragma unroll
    for (int o = 16; o > 0; o >>= 1) s += __shfl_xor_sync(0xffffffffu, s, o);
    if (lid == 0) ss[wid] = s;
    __syncthreads();
    float tot = 0.f;
#pragma unroll
    for (int i = 0; i < 8; i++) tot += ss[i];
    float inv = 1.0f / tot;
    size_t i0 = (size_t)row * RR + t;
    size_t i1 = i0 + 256;
    bf16 h, l;
    bf16split(e0 * inv, h, l);
    g_fss_h[i0] = h; g_fss_l[i0] = l;
    bf16split(e1 * inv, h, l);
    g_fss_h[i1] = h; g_fss_l[i1] = l;
}

// ---------------------------------------------------------------------------
extern "C" void kernel_launch(void* const* d_in, const int* in_sizes, int n_in,
                              void* d_out, int out_size) {
    const float* query   = (const float*)d_in[0];   // (B,L,D)
    const float* Wq      = (const float*)d_in[1];   // (D,D)
    const float* bq      = (const float*)d_in[2];   // (D,)
    const float* Wc      = (const float*)d_in[3];   // (R,L)
    const float* bc      = (const float*)d_in[4];   // (R,)
    const float* centers = (const float*)d_in[5];   // (R,D)
    const float* widths  = (const float*)d_in[6];   // (R,D)
    float* out = (float*)d_out;                     // (B,L,D)

    cudaFuncSetAttribute(gemm_bf16s<0>, cudaFuncAttributeMaxDynamicSharedMemorySize, GEMM_SMEM);
    cudaFuncSetAttribute(gemm_bf16s<1>, cudaFuncAttributeMaxDynamicSharedMemorySize, GEMM_SMEM);
    cudaFuncSetAttribute(gemm_bf16s<2>, cudaFuncAttributeMaxDynamicSharedMemorySize, GEMM_SMEM);
    cudaFuncSetAttribute(gemm_bf16s<3>, cudaFuncAttributeMaxDynamicSharedMemorySize, GEMM_SMEM);

    bf16 *qh, *ql, *wqh, *wql, *wch, *wcl, *qTh, *qTl, *qch, *qcl;
    bf16 *bch_, *bcl_, *fh, *fl, *cth, *ctl;
    float *zp, *ccp;
    cudaGetSymbolAddress((void**)&qh, g_query_h);
    cudaGetSymbolAddress((void**)&ql, g_query_l);
    cudaGetSymbolAddress((void**)&wqh, g_wq_h);
    cudaGetSymbolAddress((void**)&wql, g_wq_l);
    cudaGetSymbolAddress((void**)&wch, g_wc_h);
    cudaGetSymbolAddress((void**)&wcl, g_wc_l);
    cudaGetSymbolAddress((void**)&qTh, g_qT_h);
    cudaGetSymbolAddress((void**)&qTl, g_qT_l);
    cudaGetSymbolAddress((void**)&qch, g_qcat_h);
    cudaGetSymbolAddress((void**)&qcl, g_qcat_l);
    cudaGetSymbolAddress((void**)&bch_, g_bcat_h);
    cudaGetSymbolAddress((void**)&bcl_, g_bcat_l);
    cudaGetSymbolAddress((void**)&fh, g_fss_h);
    cudaGetSymbolAddress((void**)&fl, g_fss_l);
    cudaGetSymbolAddress((void**)&cth, g_conqT_h);
    cudaGetSymbolAddress((void**)&ctl, g_conqT_l);
    cudaGetSymbolAddress((void**)&zp, g_z);
    cudaGetSymbolAddress((void**)&ccp, g_cc);

    // prep: weights split + query dual split + rule params
    {
        int n4 = (DD * DD) / 4;
        split_kernel<<<(n4 + 255) / 256, 256>>>(Wq, wqh, wql, n4);
        n4 = (RR * LL) / 4;
        split_kernel<<<(n4 + 255) / 256, 256>>>(Wc, wch, wcl, n4);
    }
    prep_kernel<<<RR, 128>>>(centers, widths);
    {
        dim3 g(LL / 32, DD / 32, BB);
        dim3 b(32, 8);
        query_prep_kernel<<<g, b>>>(query);
    }

    // G1: q = query @ Wq^T + bq -> qcat = [q^2 | q] split   (M=M1,N=D,K=D)
    {
        dim3 g(DD / 128, M1 / 128, 1);
        gemm_bf16s<0><<<g, 256, GEMM_SMEM>>>(qh, ql, DD, 0, wqh, wql, DD, 0,
                                             nullptr, qch, qcl, 1024, 0, bq, DD);
    }
    // G2: z = scale * (qcat @ bcat^T + cc)   (M=M1,N=R,K=1024)
    {
        dim3 g(RR / 128, M1 / 128, 1);
        gemm_bf16s<1><<<g, 256, GEMM_SMEM>>>(qch, qcl, 1024, 0, bch_, bcl_, 1024, 0,
                                             zp, nullptr, nullptr, RR, 0, ccp, 1024);
    }
    softmax_kernel<<<M1, 256>>>();
    // G4: conqT[b] = qT[b] @ Wc^T + bc   (M=D, N=R, K=L, batched)
    {
        dim3 g(RR / 128, DD / 128, BB);
        gemm_bf16s<2><<<g, 256, GEMM_SMEM>>>(qTh, qTl, LL, (size_t)DD * LL,
                                             wch, wcl, LL, 0,
                                             nullptr, cth, ctl, RR, (size_t)DD * RR, bc, LL);
    }
    // G5: out[b] = Fss[b] @ conqT[b]^T   (M=L, N=D, K=R, batched)
    {
        dim3 g(DD / 128, LL / 128, BB);
        gemm_bf16s<3><<<g, 256, GEMM_SMEM>>>(fh, fl, RR, (size_t)LL * RR,
                                             cth, ctl, RR, (size_t)DD * RR,
                                             out, nullptr, nullptr, DD, (size_t)LL * DD,
                                             nullptr, RR);
    }
}

// round 11
// speedup vs baseline: 1.1415x; 1.1415x over previous
#include <cuda_runtime.h>
#include <cuda_bf16.h>
#include <cuda_fp16.h>
#include <cstdint>

// Problem constants
#define BB 8
#define LL 2048
#define DD 512
#define RR 512
#define M1 (BB * LL)   // 16384 flattened (B,L)

typedef __nv_bfloat16 bf16;
typedef __nv_bfloat162 bf162;

__device__ __forceinline__ uint32_t smem_to_u32(const void* smem_ptr) {
    uint32_t addr;
    asm("{ .reg .u64 tmp; cvta.to.shared.u64 tmp, %1; cvt.u32.u64 %0, tmp; }"
        : "=r"(addr) : "l"(smem_ptr));
    return addr;
}

__device__ __forceinline__ void bf16split(float x, bf16& h, bf16& l) {
    h = __float2bfloat16(x);
    l = __float2bfloat16(x - __bfloat162float(h));
}

__device__ __forceinline__ void f16split(float x, __half& h, __half& l) {
    h = __float2half(x);
    l = __float2half(x - __half2float(h));
}

#define CPASYNC16(dst, src) \
    asm volatile("cp.async.cg.shared.global [%0], [%1], 16;" :: "r"(dst), "l"(src))
#define CPASYNC_COMMIT() asm volatile("cp.async.commit_group;" ::: "memory")

#define LDSM4(r0, r1, r2, r3, addr) \
    asm volatile("ldmatrix.sync.aligned.m8n8.x4.shared.b16 {%0,%1,%2,%3}, [%4];" \
                 : "=r"(r0), "=r"(r1), "=r"(r2), "=r"(r3) : "r"(addr))

__device__ __forceinline__ void mma_bf(float* c, const uint32_t* a, const uint32_t* b) {
    asm volatile("mma.sync.aligned.m16n8k16.row.col.f32.bf16.bf16.f32 "
                 "{%0,%1,%2,%3}, {%4,%5,%6,%7}, {%8,%9}, {%0,%1,%2,%3};"
                 : "+f"(c[0]), "+f"(c[1]), "+f"(c[2]), "+f"(c[3])
                 : "r"(a[0]), "r"(a[1]), "r"(a[2]), "r"(a[3]),
                   "r"(b[0]), "r"(b[1]));
}
__device__ __forceinline__ void mma_hf(float* c, const uint32_t* a, const uint32_t* b) {
    asm volatile("mma.sync.aligned.m16n8k16.row.col.f32.f16.f16.f32 "
                 "{%0,%1,%2,%3}, {%4,%5,%6,%7}, {%8,%9}, {%0,%1,%2,%3};"
                 : "+f"(c[0]), "+f"(c[1]), "+f"(c[2]), "+f"(c[3])
                 : "r"(a[0]), "r"(a[1]), "r"(a[2]), "r"(a[3]),
                   "r"(b[0]), "r"(b[1]));
}

// ---------------- scratch (device globals; no allocation allowed) ----------
__device__ bf16   g_query_h[(size_t)M1 * DD];
__device__ bf16   g_query_l[(size_t)M1 * DD];
__device__ bf16   g_wq_h[DD * DD];
__device__ bf16   g_wq_l[DD * DD];
__device__ bf16   g_qcat_h[(size_t)M1 * 1024];   // [q^2 | q]
__device__ bf16   g_qcat_l[(size_t)M1 * 1024];
__device__ bf16   g_bcat_h[RR * 1024];           // [invw2 | -2c*invw2]
__device__ bf16   g_bcat_l[RR * 1024];
__device__ float  g_z[(size_t)M1 * RR];
__device__ float  g_cc[RR];
// fp16 path (G4/G5)
__device__ __half g_qT16[(size_t)BB * DD * LL];  // transposed query, fp16 single
__device__ __half g_wc16h[RR * LL];
__device__ __half g_wc16l[RR * LL];
__device__ __half g_fss16[(size_t)M1 * RR];
__device__ __half g_cq16h[(size_t)BB * DD * RR]; // conqT fp16 split
__device__ __half g_cq16l[(size_t)BB * DD * RR];

// ---------------------------------------------------------------------------
// split: fp32 -> (hi, lo) bf16 (for Wq)
// ---------------------------------------------------------------------------
__global__ void split_kernel(const float* __restrict__ src, bf16* __restrict__ hi,
                             bf16* __restrict__ lo, int n4) {
    int i = blockIdx.x * blockDim.x + threadIdx.x;
    if (i >= n4) return;
    float4 v = ((const float4*)src)[i];
    bf16 h0, l0, h1, l1, h2, l2, h3, l3;
    bf16split(v.x, h0, l0); bf16split(v.y, h1, l1);
    bf16split(v.z, h2, l2); bf16split(v.w, h3, l3);
    bf162 hh0; hh0.x = h0; hh0.y = h1;
    bf162 hh1; hh1.x = h2; hh1.y = h3;
    bf162 ll0; ll0.x = l0; ll0.y = l1;
    bf162 ll1; ll1.x = l2; ll1.y = l3;
    ((bf162*)hi)[i * 2 + 0] = hh0;
    ((bf162*)hi)[i * 2 + 1] = hh1;
    ((bf162*)lo)[i * 2 + 0] = ll0;
    ((bf162*)lo)[i * 2 + 1] = ll1;
}

// ---------------------------------------------------------------------------
// split16: fp32 -> (hi, lo) fp16 (for Wc)
// ---------------------------------------------------------------------------
__global__ void split16_kernel(const float* __restrict__ src, __half* __restrict__ hi,
                               __half* __restrict__ lo, int n4) {
    int i = blockIdx.x * blockDim.x + threadIdx.x;
    if (i >= n4) return;
    float4 v = ((const float4*)src)[i];
    __half h0, l0, h1, l1, h2, l2, h3, l3;
    f16split(v.x, h0, l0); f16split(v.y, h1, l1);
    f16split(v.z, h2, l2); f16split(v.w, h3, l3);
    __half2 a0; a0.x = h0; a0.y = h1;
    __half2 a1; a1.x = h2; a1.y = h3;
    __half2 b0; b0.x = l0; b0.y = l1;
    __half2 b1; b1.x = l2; b1.y = l3;
    ((__half2*)hi)[i * 2 + 0] = a0;
    ((__half2*)hi)[i * 2 + 1] = a1;
    ((__half2*)lo)[i * 2 + 0] = b0;
    ((__half2*)lo)[i * 2 + 1] = b1;
}

// ---------------------------------------------------------------------------
// query prep: single read -> row-major bf16 split (G1) + transposed fp16 (G4)
// ---------------------------------------------------------------------------
__global__ void query_prep_kernel(const float* __restrict__ query) {
    __shared__ float tile[32][33];
    int b = blockIdx.z;
    int l0 = blockIdx.x * 32, d0 = blockIdx.y * 32;
    int tx = threadIdx.x, ty = threadIdx.y;
    const float* src = query + (size_t)b * LL * DD;
#pragma unroll
    for (int i = 0; i < 4; i++) {
        int l = l0 + ty + 8 * i;
        float v = src[(size_t)l * DD + d0 + tx];
        tile[ty + 8 * i][tx] = v;
        bf16 h, lw;
        bf16split(v, h, lw);
        size_t idx = (size_t)(b * LL + l) * DD + d0 + tx;
        g_query_h[idx] = h;
        g_query_l[idx] = lw;
    }
    __syncthreads();
    size_t base = (size_t)b * DD * LL;
#pragma unroll
    for (int i = 0; i < 4; i++) {
        float v = tile[tx][ty + 8 * i];
        size_t idx = base + (size_t)(d0 + ty + 8 * i) * LL + l0 + tx;
        g_qT16[idx] = __float2half(v);
    }
}

// ---------------------------------------------------------------------------
// prep: bcat = [invw2 | -2c*invw2] split bf16, cc[r] = sum c^2*invw2
// ---------------------------------------------------------------------------
__global__ void prep_kernel(const float* __restrict__ centers,
                            const float* __restrict__ widths) {
    int r = blockIdx.x;
    int t = threadIdx.x;  // 128
    float acc = 0.f;
    for (int d = t; d < DD; d += 128) {
        float w = widths[r * DD + d];
        float c = centers[r * DD + d];
        float iw = 1.0f / (w * w);
        float b2 = -2.0f * c * iw;
        bf16 h, l;
        bf16split(iw, h, l);
        g_bcat_h[r * 1024 + d] = h;
        g_bcat_l[r * 1024 + d] = l;
        bf16split(b2, h, l);
        g_bcat_h[r * 1024 + 512 + d] = h;
        g_bcat_l[r * 1024 + 512 + d] = l;
        acc += c * c * iw;
    }
    __shared__ float sred[128];
    sred[t] = acc;
    __syncthreads();
    for (int s = 64; s > 0; s >>= 1) {
        if (t < s) sred[t] += sred[t + s];
        __syncthreads();
    }
    if (t == 0) g_cc[r] = sred[0];
}

// ---------------------------------------------------------------------------
// Split-precision NT GEMM via mma.sync m16n8k16.
//   F16=false: bf16 3-pass (AhBh + AhBl + AlBh), 4 tiles/stage.
//   F16=true : fp16 2-pass (A·Bh + A·Bl), A single fp16, 3 tiles/stage.
// 128x128 CTA tile, 8 warps of 64x32. K-chunk 64, 2-stage cp.async pipeline.
// SMEM tile: 128 rows x 128B data, 144B pitch (conflict-free ldmatrix+store).
// MODE 0: qcat ((v+aux)^2 | (v+aux), bf16 split; ldc=1024)
// MODE 1: fp32 scale*(v+aux[n]) -> Cf
// MODE 2: fp16 split v+aux[n]   -> Ch/Cl (as __half*)
// MODE 3: fp32 raw              -> Cf
// ---------------------------------------------------------------------------
#define TPITCH 144
#define TILE_B (128 * TPITCH)        // 18432

template <int MODE, bool F16>
__global__ __launch_bounds__(256, 1) void gemm_s(
    const uint16_t* __restrict__ Ah, const uint16_t* __restrict__ Al, int lda, size_t sA,
    const uint16_t* __restrict__ Bh, const uint16_t* __restrict__ Bl, int ldb, size_t sB,
    float* __restrict__ Cf, void* __restrict__ Chv, void* __restrict__ Clv,
    int ldc, size_t sC, const float* __restrict__ aux, int K) {
    constexpr uint32_t STB = (F16 ? 3 : 4) * TILE_B;
    constexpr uint32_t OFF_BH = F16 ? TILE_B : 2 * TILE_B;
    constexpr uint32_t OFF_BL = F16 ? 2 * TILE_B : 3 * TILE_B;
    extern __shared__ char smem[];
    uint32_t sb = smem_to_u32(smem);
    int t = threadIdx.x;
    int lane = t & 31, wid = t >> 5;
    int wm = wid & 1, wn = wid >> 1;
    int bn = blockIdx.x * 128, bm = blockIdx.y * 128;
    size_t bz = blockIdx.z;
    Ah += bz * sA;
    Bh += bz * sB; Bl += bz * sB;
    const uint16_t* AlB = F16 ? Ah : (Al + bz * sA);   // dummy when F16

    // cp.async plan: each thread covers rows r0+32i, one 16B column, per tile.
    int r0 = t >> 3;
    int cc = t & 7;
    const uint16_t* gA_h = Ah + (size_t)(bm + r0) * lda + cc * 8;
    const uint16_t* gA_l = AlB + (size_t)(bm + r0) * lda + cc * 8;
    const uint16_t* gB_h = Bh + (size_t)(bn + r0) * ldb + cc * 8;
    const uint16_t* gB_l = Bl + (size_t)(bn + r0) * ldb + cc * 8;
    uint32_t soff = (uint32_t)(r0 * TPITCH + cc * 16);

    float acc[4][4][4] = {};
    const int nk = K >> 6;

    // prologue: chunk 0 -> stage 0
    {
        uint32_t db = sb;
#pragma unroll
        for (int i = 0; i < 4; i++) {
            uint32_t o = soff + (uint32_t)(i * 32 * TPITCH);
            size_t ga = (size_t)(32 * i) * lda;
            size_t gb = (size_t)(32 * i) * ldb;
            CPASYNC16(db + o, gA_h + ga);
            if (!F16) CPASYNC16(db + TILE_B + o, gA_l + ga);
            CPASYNC16(db + OFF_BH + o, gB_h + gb);
            CPASYNC16(db + OFF_BL + o, gB_l + gb);
        }
        CPASYNC_COMMIT();
    }

    int lm = lane & 15, lq = lane >> 4;
    uint32_t a_base = (uint32_t)((wm * 64 + lm) * TPITCH);
    uint32_t b_base = (uint32_t)((wn * 32 + lm) * TPITCH);

    for (int kt = 0; kt < nk; kt++) {
        int buf = kt & 1;
        if (kt + 1 < nk) {
            uint32_t db = sb + (buf ^ 1) * STB;
            int koff = (kt + 1) * 64;
#pragma unroll
            for (int i = 0; i < 4; i++) {
                uint32_t o = soff + (uint32_t)(i * 32 * TPITCH);
                size_t ga = (size_t)(32 * i) * lda + koff;
                size_t gb = (size_t)(32 * i) * ldb + koff;
                CPASYNC16(db + o, gA_h + ga);
                if (!F16) CPASYNC16(db + TILE_B + o, gA_l + ga);
                CPASYNC16(db + OFF_BH + o, gB_h + gb);
                CPASYNC16(db + OFF_BL + o, gB_l + gb);
            }
            CPASYNC_COMMIT();
            asm volatile("cp.async.wait_group 1;" ::: "memory");
        } else {
            asm volatile("cp.async.wait_group 0;" ::: "memory");
        }
        __syncthreads();
        uint32_t base = sb + buf * STB;
#pragma unroll
        for (int ks = 0; ks < 4; ks++) {
            uint32_t off16 = (uint32_t)((2 * ks + lq) * 16);
            uint32_t a[4][4], bh[4][2], bl[4][2];
#pragma unroll
            for (int i = 0; i < 4; i++)
                LDSM4(a[i][0], a[i][1], a[i][2], a[i][3],
                      base + a_base + i * (16 * TPITCH) + off16);
#pragma unroll
            for (int jj = 0; jj < 2; jj++) {
                uint32_t q0, q1, q2, q3;
                LDSM4(q0, q1, q2, q3,
                      base + OFF_BH + b_base + jj * (16 * TPITCH) + off16);
                bh[2 * jj][0] = q0; bh[2 * jj][1] = q2;
                bh[2 * jj + 1][0] = q1; bh[2 * jj + 1][1] = q3;
            }
#pragma unroll
            for (int i = 0; i < 4; i++)
#pragma unroll
                for (int j = 0; j < 4; j++) {
                    if (F16) mma_hf(acc[i][j], a[i], bh[j]);
                    else     mma_bf(acc[i][j], a[i], bh[j]);
                }
#pragma unroll
            for (int jj = 0; jj < 2; jj++) {
                uint32_t q0, q1, q2, q3;
                LDSM4(q0, q1, q2, q3,
                      base + OFF_BL + b_base + jj * (16 * TPITCH) + off16);
                bl[2 * jj][0] = q0; bl[2 * jj][1] = q2;
                bl[2 * jj + 1][0] = q1; bl[2 * jj + 1][1] = q3;
            }
#pragma unroll
            for (int i = 0; i < 4; i++)
#pragma unroll
                for (int j = 0; j < 4; j++) {
                    if (F16) mma_hf(acc[i][j], a[i], bl[j]);
                    else     mma_bf(acc[i][j], a[i], bl[j]);
                }
            if (!F16) {
#pragma unroll
                for (int i = 0; i < 4; i++)
                    LDSM4(a[i][0], a[i][1], a[i][2], a[i][3],
                          base + TILE_B + a_base + i * (16 * TPITCH) + off16);
#pragma unroll
                for (int i = 0; i < 4; i++)
#pragma unroll
                    for (int j = 0; j < 4; j++) mma_bf(acc[i][j], a[i], bh[j]);
            }
        }
        __syncthreads();
    }

    // epilogue (register-direct)
    int rbase = bm + wm * 64 + (lane >> 2);
    int nbase = bn + wn * 32 + (lane & 3) * 2;
#pragma unroll
    for (int i = 0; i < 4; i++) {
#pragma unroll
        for (int j = 0; j < 4; j++) {
            int n = nbase + j * 8;
#pragma unroll
            for (int h = 0; h < 2; h++) {
                int m = rbase + i * 16 + h * 8;
                float v0 = acc[i][j][2 * h];
                float v1 = acc[i][j][2 * h + 1];
                if (MODE == 0) {
                    bf16* Ch = (bf16*)Chv;
                    bf16* Cl = (bf16*)Clv;
                    size_t crow = (size_t)m * ldc;
                    float q0 = v0 + aux[n], q1 = v1 + aux[n + 1];
                    bf16 h0, l0, h1, l1;
                    bf16split(q0 * q0, h0, l0); bf16split(q1 * q1, h1, l1);
                    bf162 hh; hh.x = h0; hh.y = h1;
                    bf162 ll; ll.x = l0; ll.y = l1;
                    *(bf162*)(Ch + crow + n) = hh;
                    *(bf162*)(Cl + crow + n) = ll;
                    bf16split(q0, h0, l0); bf16split(q1, h1, l1);
                    hh.x = h0; hh.y = h1; ll.x = l0; ll.y = l1;
                    *(bf162*)(Ch + crow + 512 + n) = hh;
                    *(bf162*)(Cl + crow + 512 + n) = ll;
                } else if (MODE == 1) {
                    const float scale = -0.5f / (float)DD;
                    size_t crow = (size_t)m * ldc;
                    float2 o;
                    o.x = scale * (v0 + aux[n]);
                    o.y = scale * (v1 + aux[n + 1]);
                    *(float2*)(Cf + crow + n) = o;
                } else if (MODE == 2) {
                    __half* Ch = (__half*)Chv;
                    __half* Cl = (__half*)Clv;
                    size_t crow = bz * sC + (size_t)m * ldc;
                    float q0 = v0 + aux[n], q1 = v1 + aux[n + 1];
                    __half h0, l0, h1, l1;
                    f16split(q0, h0, l0); f16split(q1, h1, l1);
                    __half2 hh; hh.x = h0; hh.y = h1;
                    __half2 ll; ll.x = l0; ll.y = l1;
                    *(__half2*)(Ch + crow + n) = hh;
                    *(__half2*)(Cl + crow + n) = ll;
                } else {
                    size_t crow = bz * sC + (size_t)m * ldc;
                    float2 o; o.x = v0; o.y = v1;
                    *(float2*)(Cf + crow + n) = o;
                }
            }
        }
    }
}

// ---------------------------------------------------------------------------
// softmax over R: reads fp32 g_z (scaled logits), writes fp16 Fss
// ---------------------------------------------------------------------------
__global__ void softmax_kernel() {
    int row = blockIdx.x;
    int t = threadIdx.x;  // 256
    const float* zrow = g_z + (size_t)row * RR;
    float v0 = zrow[t];
    float v1 = zrow[t + 256];
    float m = fmaxf(v0, v1);
#pragma unroll
    for (int o = 16; o > 0; o >>= 1) m = fmaxf(m, __shfl_xor_sync(0xffffffffu, m, o));
    __shared__ float sm[8];
    __shared__ float ss[8];
    int wid = t >> 5, lid = t & 31;
    if (lid == 0) sm[wid] = m;
    __syncthreads();
    float mm = sm[0];
#pragma unroll
    for (int i = 1; i < 8; i++) mm = fmaxf(mm, sm[i]);
    float e0 = __expf(v0 - mm), e1 = __expf(v1 - mm);
    float s = e0 + e1;
#pragma unroll
    for (int o = 16; o > 0; o >>= 1) s += __shfl_xor_sync(0xffffffffu, s, o);
    if (lid == 0) ss[wid] = s;
    __syncthreads();
    float tot = 0.f;
#pragma unroll
    for (int i = 0; i < 8; i++) tot += ss[i];
    float inv = 1.0f / tot;
    size_t i0 = (size_t)row * RR + t;
    g_fss16[i0] = __float2half(e0 * inv);
    g_fss16[i0 + 256] = __float2half(e1 * inv);
}

// ---------------------------------------------------------------------------
extern "C" void kernel_launch(void* const* d_in, const int* in_sizes, int n_in,
                              void* d_out, int out_size) {
    const float* query   = (const float*)d_in[0];   // (B,L,D)
    const float* Wq      = (const float*)d_in[1];   // (D,D)
    const float* bq      = (const float*)d_in[2];   // (D,)
    const float* Wc      = (const float*)d_in[3];   // (R,L)
    const float* bc      = (const float*)d_in[4];   // (R,)
    const float* centers = (const float*)d_in[5];   // (R,D)
    const float* widths  = (const float*)d_in[6];   // (R,D)
    float* out = (float*)d_out;                     // (B,L,D)

    const int SMEM_BF = 2 * 4 * TILE_B;   // 147456
    const int SMEM_HF = 2 * 3 * TILE_B;   // 110592
    cudaFuncSetAttribute(gemm_s<0, false>, cudaFuncAttributeMaxDynamicSharedMemorySize, SMEM_BF);
    cudaFuncSetAttribute(gemm_s<1, false>, cudaFuncAttributeMaxDynamicSharedMemorySize, SMEM_BF);
    cudaFuncSetAttribute(gemm_s<2, true>,  cudaFuncAttributeMaxDynamicSharedMemorySize, SMEM_HF);
    cudaFuncSetAttribute(gemm_s<3, true>,  cudaFuncAttributeMaxDynamicSharedMemorySize, SMEM_HF);

    bf16 *qh, *ql, *wqh, *wql, *qch, *qcl, *bch_, *bcl_;
    __half *qT16, *wc16h, *wc16l, *fss16, *cq16h, *cq16l;
    float *zp, *ccp;
    cudaGetSymbolAddress((void**)&qh, g_query_h);
    cudaGetSymbolAddress((void**)&ql, g_query_l);
    cudaGetSymbolAddress((void**)&wqh, g_wq_h);
    cudaGetSymbolAddress((void**)&wql, g_wq_l);
    cudaGetSymbolAddress((void**)&qch, g_qcat_h);
    cudaGetSymbolAddress((void**)&qcl, g_qcat_l);
    cudaGetSymbolAddress((void**)&bch_, g_bcat_h);
    cudaGetSymbolAddress((void**)&bcl_, g_bcat_l);
    cudaGetSymbolAddress((void**)&qT16, g_qT16);
    cudaGetSymbolAddress((void**)&wc16h, g_wc16h);
    cudaGetSymbolAddress((void**)&wc16l, g_wc16l);
    cudaGetSymbolAddress((void**)&fss16, g_fss16);
    cudaGetSymbolAddress((void**)&cq16h, g_cq16h);
    cudaGetSymbolAddress((void**)&cq16l, g_cq16l);
    cudaGetSymbolAddress((void**)&zp, g_z);
    cudaGetSymbolAddress((void**)&ccp, g_cc);

    // prep: weight splits + query dual-format + rule params
    {
        int n4 = (DD * DD) / 4;
        split_kernel<<<(n4 + 255) / 256, 256>>>(Wq, wqh, wql, n4);
        n4 = (RR * LL) / 4;
        split16_kernel<<<(n4 + 255) / 256, 256>>>(Wc, wc16h, wc16l, n4);
    }
    prep_kernel<<<RR, 128>>>(centers, widths);
    {
        dim3 g(LL / 32, DD / 32, BB);
        dim3 b(32, 8);
        query_prep_kernel<<<g, b>>>(query);
    }

    // G1 (bf16 3-pass): q = query @ Wq^T + bq -> qcat = [q^2 | q]
    {
        dim3 g(DD / 128, M1 / 128, 1);
        gemm_s<0, false><<<g, 256, SMEM_BF>>>(
            (const uint16_t*)qh, (const uint16_t*)ql, DD, 0,
            (const uint16_t*)wqh, (const uint16_t*)wql, DD, 0,
            nullptr, qch, qcl, 1024, 0, bq, DD);
    }
    // G2 (bf16 3-pass): z = scale * (qcat @ bcat^T + cc)   (K=1024)
    {
        dim3 g(RR / 128, M1 / 128, 1);
        gemm_s<1, false><<<g, 256, SMEM_BF>>>(
            (const uint16_t*)qch, (const uint16_t*)qcl, 1024, 0,
            (const uint16_t*)bch_, (const uint16_t*)bcl_, 1024, 0,
            zp, nullptr, nullptr, RR, 0, ccp, 1024);
    }
    softmax_kernel<<<M1, 256>>>();
    // G4 (fp16 2-pass): conqT[b] = qT[b] @ Wc^T + bc  (M=D, N=R, K=L)
    {
        dim3 g(RR / 128, DD / 128, BB);
        gemm_s<2, true><<<g, 256, SMEM_HF>>>(
            (const uint16_t*)qT16, nullptr, LL, (size_t)DD * LL,
            (const uint16_t*)wc16h, (const uint16_t*)wc16l, LL, 0,
            nullptr, cq16h, cq16l, RR, (size_t)DD * RR, bc, LL);
    }
    // G5 (fp16 2-pass): out[b] = Fss[b] @ conqT[b]^T  (M=L, N=D, K=R)
    {
        dim3 g(DD / 128, LL / 128, BB);
        gemm_s<3, true><<<g, 256, SMEM_HF>>>(
            (const uint16_t*)fss16, nullptr, RR, (size_t)LL * RR,
            (const uint16_t*)cq16h, (const uint16_t*)cq16l, RR, (size_t)DD * RR,
            out, nullptr, nullptr, DD, (size_t)LL * DD, nullptr, RR);
    }
}

// round 12
// speedup vs baseline: 1.3922x; 1.2196x over previous
#include <cuda_runtime.h>
#include <cuda_bf16.h>
#include <cuda_fp16.h>
#include <cstdint>

// Problem constants
#define BB 8
#define LL 2048
#define DD 512
#define RR 512
#define M1 (BB * LL)   // 16384 flattened (B,L)

typedef __nv_bfloat16 bf16;
typedef __nv_bfloat162 bf162;

__device__ __forceinline__ uint32_t smem_to_u32(const void* smem_ptr) {
    uint32_t addr;
    asm("{ .reg .u64 tmp; cvta.to.shared.u64 tmp, %1; cvt.u32.u64 %0, tmp; }"
        : "=r"(addr) : "l"(smem_ptr));
    return addr;
}

__device__ __forceinline__ void bf16split(float x, bf16& h, bf16& l) {
    h = __float2bfloat16(x);
    l = __float2bfloat16(x - __bfloat162float(h));
}

__device__ __forceinline__ void f16split(float x, __half& h, __half& l) {
    h = __float2half(x);
    l = __float2half(x - __half2float(h));
}

#define CPASYNC16(dst, src) \
    asm volatile("cp.async.cg.shared.global [%0], [%1], 16;" :: "r"(dst), "l"(src))
#define CPASYNC_COMMIT() asm volatile("cp.async.commit_group;" ::: "memory")

#define LDSM4(r0, r1, r2, r3, addr) \
    asm volatile("ldmatrix.sync.aligned.m8n8.x4.shared.b16 {%0,%1,%2,%3}, [%4];" \
                 : "=r"(r0), "=r"(r1), "=r"(r2), "=r"(r3) : "r"(addr))

__device__ __forceinline__ void mma_bf(float* c, const uint32_t* a, const uint32_t* b) {
    asm volatile("mma.sync.aligned.m16n8k16.row.col.f32.bf16.bf16.f32 "
                 "{%0,%1,%2,%3}, {%4,%5,%6,%7}, {%8,%9}, {%0,%1,%2,%3};"
                 : "+f"(c[0]), "+f"(c[1]), "+f"(c[2]), "+f"(c[3])
                 : "r"(a[0]), "r"(a[1]), "r"(a[2]), "r"(a[3]),
                   "r"(b[0]), "r"(b[1]));
}
__device__ __forceinline__ void mma_hf(float* c, const uint32_t* a, const uint32_t* b) {
    asm volatile("mma.sync.aligned.m16n8k16.row.col.f32.f16.f16.f32 "
                 "{%0,%1,%2,%3}, {%4,%5,%6,%7}, {%8,%9}, {%0,%1,%2,%3};"
                 : "+f"(c[0]), "+f"(c[1]), "+f"(c[2]), "+f"(c[3])
                 : "r"(a[0]), "r"(a[1]), "r"(a[2]), "r"(a[3]),
                   "r"(b[0]), "r"(b[1]));
}

// ---------------- scratch (device globals; no allocation allowed) ----------
__device__ bf16   g_query_h[(size_t)M1 * DD];
__device__ bf16   g_query_l[(size_t)M1 * DD];
__device__ bf16   g_wq_h[DD * DD];
__device__ bf16   g_wq_l[DD * DD];
__device__ __half g_qcat16[(size_t)M1 * 1024];   // [q^2 | q], fp16 single
__device__ __half g_bcat16h[RR * 1024];          // [invw2 | -2c*invw2] fp16 split
__device__ __half g_bcat16l[RR * 1024];
__device__ float  g_z[(size_t)M1 * RR];
__device__ float  g_cc[RR];
// fp16 path (G4/G5)
__device__ __half g_qT16[(size_t)BB * DD * LL];  // transposed query, fp16 single
__device__ __half g_wc16h[RR * LL];
__device__ __half g_wc16l[RR * LL];
__device__ __half g_fss16[(size_t)M1 * RR];
__device__ __half g_cq16h[(size_t)BB * DD * RR]; // conqT fp16 split
__device__ __half g_cq16l[(size_t)BB * DD * RR];

// ---------------------------------------------------------------------------
// split: fp32 -> (hi, lo) bf16 (for Wq)
// ---------------------------------------------------------------------------
__global__ void split_kernel(const float* __restrict__ src, bf16* __restrict__ hi,
                             bf16* __restrict__ lo, int n4) {
    int i = blockIdx.x * blockDim.x + threadIdx.x;
    if (i >= n4) return;
    float4 v = ((const float4*)src)[i];
    bf16 h0, l0, h1, l1, h2, l2, h3, l3;
    bf16split(v.x, h0, l0); bf16split(v.y, h1, l1);
    bf16split(v.z, h2, l2); bf16split(v.w, h3, l3);
    bf162 hh0; hh0.x = h0; hh0.y = h1;
    bf162 hh1; hh1.x = h2; hh1.y = h3;
    bf162 ll0; ll0.x = l0; ll0.y = l1;
    bf162 ll1; ll1.x = l2; ll1.y = l3;
    ((bf162*)hi)[i * 2 + 0] = hh0;
    ((bf162*)hi)[i * 2 + 1] = hh1;
    ((bf162*)lo)[i * 2 + 0] = ll0;
    ((bf162*)lo)[i * 2 + 1] = ll1;
}

// ---------------------------------------------------------------------------
// split16: fp32 -> (hi, lo) fp16 (for Wc)
// ---------------------------------------------------------------------------
__global__ void split16_kernel(const float* __restrict__ src, __half* __restrict__ hi,
                               __half* __restrict__ lo, int n4) {
    int i = blockIdx.x * blockDim.x + threadIdx.x;
    if (i >= n4) return;
    float4 v = ((const float4*)src)[i];
    __half h0, l0, h1, l1, h2, l2, h3, l3;
    f16split(v.x, h0, l0); f16split(v.y, h1, l1);
    f16split(v.z, h2, l2); f16split(v.w, h3, l3);
    __half2 a0; a0.x = h0; a0.y = h1;
    __half2 a1; a1.x = h2; a1.y = h3;
    __half2 b0; b0.x = l0; b0.y = l1;
    __half2 b1; b1.x = l2; b1.y = l3;
    ((__half2*)hi)[i * 2 + 0] = a0;
    ((__half2*)hi)[i * 2 + 1] = a1;
    ((__half2*)lo)[i * 2 + 0] = b0;
    ((__half2*)lo)[i * 2 + 1] = b1;
}

// ---------------------------------------------------------------------------
// query prep: single read -> row-major bf16 split (G1) + transposed fp16 (G4)
// ---------------------------------------------------------------------------
__global__ void query_prep_kernel(const float* __restrict__ query) {
    __shared__ float tile[32][33];
    int b = blockIdx.z;
    int l0 = blockIdx.x * 32, d0 = blockIdx.y * 32;
    int tx = threadIdx.x, ty = threadIdx.y;
    const float* src = query + (size_t)b * LL * DD;
#pragma unroll
    for (int i = 0; i < 4; i++) {
        int l = l0 + ty + 8 * i;
        float v = src[(size_t)l * DD + d0 + tx];
        tile[ty + 8 * i][tx] = v;
        bf16 h, lw;
        bf16split(v, h, lw);
        size_t idx = (size_t)(b * LL + l) * DD + d0 + tx;
        g_query_h[idx] = h;
        g_query_l[idx] = lw;
    }
    __syncthreads();
    size_t base = (size_t)b * DD * LL;
#pragma unroll
    for (int i = 0; i < 4; i++) {
        float v = tile[tx][ty + 8 * i];
        size_t idx = base + (size_t)(d0 + ty + 8 * i) * LL + l0 + tx;
        g_qT16[idx] = __float2half(v);
    }
}

// ---------------------------------------------------------------------------
// prep: bcat = [invw2 | -2c*invw2] fp16 split, cc[r] = sum c^2*invw2
// ---------------------------------------------------------------------------
__global__ void prep_kernel(const float* __restrict__ centers,
                            const float* __restrict__ widths) {
    int r = blockIdx.x;
    int t = threadIdx.x;  // 128
    float acc = 0.f;
    for (int d = t; d < DD; d += 128) {
        float w = widths[r * DD + d];
        float c = centers[r * DD + d];
        float iw = 1.0f / (w * w);
        float b2 = -2.0f * c * iw;
        __half h, l;
        f16split(iw, h, l);
        g_bcat16h[r * 1024 + d] = h;
        g_bcat16l[r * 1024 + d] = l;
        f16split(b2, h, l);
        g_bcat16h[r * 1024 + 512 + d] = h;
        g_bcat16l[r * 1024 + 512 + d] = l;
        acc += c * c * iw;
    }
    __shared__ float sred[128];
    sred[t] = acc;
    __syncthreads();
    for (int s = 64; s > 0; s >>= 1) {
        if (t < s) sred[t] += sred[t + s];
        __syncthreads();
    }
    if (t == 0) g_cc[r] = sred[0];
}

// ---------------------------------------------------------------------------
// Split-precision NT GEMM via mma.sync m16n8k16.
//   F16=false: bf16 3-pass (AhBh + AhBl + AlBh), 4 tiles/stage.
//   F16=true : fp16 2-pass (A·Bh + A·Bl), A single fp16, 3 tiles/stage.
// 128x128 CTA tile, 8 warps of 64x32. K-chunk 64, 2-stage cp.async pipeline.
// SMEM tile: 128 rows x 128B data, 144B pitch (conflict-free ldmatrix+store).
// MODE 0: qcat ((v+aux)^2 | (v+aux)) -> single fp16 (Chv; ldc=1024)
// MODE 1: fp32 scale*(v+aux[n]) -> Cf
// MODE 2: fp16 split v+aux[n]   -> Chv/Clv (as __half*)
// MODE 3: fp32 raw              -> Cf
// ---------------------------------------------------------------------------
#define TPITCH 144
#define TILE_B (128 * TPITCH)        // 18432

template <int MODE, bool F16>
__global__ __launch_bounds__(256, 1) void gemm_s(
    const uint16_t* __restrict__ Ah, const uint16_t* __restrict__ Al, int lda, size_t sA,
    const uint16_t* __restrict__ Bh, const uint16_t* __restrict__ Bl, int ldb, size_t sB,
    float* __restrict__ Cf, void* __restrict__ Chv, void* __restrict__ Clv,
    int ldc, size_t sC, const float* __restrict__ aux, int K) {
    constexpr uint32_t STB = (F16 ? 3 : 4) * TILE_B;
    constexpr uint32_t OFF_BH = F16 ? TILE_B : 2 * TILE_B;
    constexpr uint32_t OFF_BL = F16 ? 2 * TILE_B : 3 * TILE_B;
    extern __shared__ char smem[];
    uint32_t sb = smem_to_u32(smem);
    int t = threadIdx.x;
    int lane = t & 31, wid = t >> 5;
    int wm = wid & 1, wn = wid >> 1;
    int bn = blockIdx.x * 128, bm = blockIdx.y * 128;
    size_t bz = blockIdx.z;
    Ah += bz * sA;
    Bh += bz * sB; Bl += bz * sB;
    const uint16_t* AlB = F16 ? Ah : (Al + bz * sA);   // dummy when F16

    // cp.async plan: each thread covers rows r0+32i, one 16B column, per tile.
    int r0 = t >> 3;
    int cc = t & 7;
    const uint16_t* gA_h = Ah + (size_t)(bm + r0) * lda + cc * 8;
    const uint16_t* gA_l = AlB + (size_t)(bm + r0) * lda + cc * 8;
    const uint16_t* gB_h = Bh + (size_t)(bn + r0) * ldb + cc * 8;
    const uint16_t* gB_l = Bl + (size_t)(bn + r0) * ldb + cc * 8;
    uint32_t soff = (uint32_t)(r0 * TPITCH + cc * 16);

    float acc[4][4][4] = {};
    const int nk = K >> 6;

    // prologue: chunk 0 -> stage 0
    {
        uint32_t db = sb;
#pragma unroll
        for (int i = 0; i < 4; i++) {
            uint32_t o = soff + (uint32_t)(i * 32 * TPITCH);
            size_t ga = (size_t)(32 * i) * lda;
            size_t gb = (size_t)(32 * i) * ldb;
            CPASYNC16(db + o, gA_h + ga);
            if (!F16) CPASYNC16(db + TILE_B + o, gA_l + ga);
            CPASYNC16(db + OFF_BH + o, gB_h + gb);
            CPASYNC16(db + OFF_BL + o, gB_l + gb);
        }
        CPASYNC_COMMIT();
    }

    int lm = lane & 15, lq = lane >> 4;
    uint32_t a_base = (uint32_t)((wm * 64 + lm) * TPITCH);
    uint32_t b_base = (uint32_t)((wn * 32 + lm) * TPITCH);

    for (int kt = 0; kt < nk; kt++) {
        int buf = kt & 1;
        if (kt + 1 < nk) {
            uint32_t db = sb + (buf ^ 1) * STB;
            int koff = (kt + 1) * 64;
#pragma unroll
            for (int i = 0; i < 4; i++) {
                uint32_t o = soff + (uint32_t)(i * 32 * TPITCH);
                size_t ga = (size_t)(32 * i) * lda + koff;
                size_t gb = (size_t)(32 * i) * ldb + koff;
                CPASYNC16(db + o, gA_h + ga);
                if (!F16) CPASYNC16(db + TILE_B + o, gA_l + ga);
                CPASYNC16(db + OFF_BH + o, gB_h + gb);
                CPASYNC16(db + OFF_BL + o, gB_l + gb);
            }
            CPASYNC_COMMIT();
            asm volatile("cp.async.wait_group 1;" ::: "memory");
        } else {
            asm volatile("cp.async.wait_group 0;" ::: "memory");
        }
        __syncthreads();
        uint32_t base = sb + buf * STB;
#pragma unroll
        for (int ks = 0; ks < 4; ks++) {
            uint32_t off16 = (uint32_t)((2 * ks + lq) * 16);
            uint32_t a[4][4], bh[4][2], bl[4][2];
#pragma unroll
            for (int i = 0; i < 4; i++)
                LDSM4(a[i][0], a[i][1], a[i][2], a[i][3],
                      base + a_base + i * (16 * TPITCH) + off16);
#pragma unroll
            for (int jj = 0; jj < 2; jj++) {
                uint32_t q0, q1, q2, q3;
                LDSM4(q0, q1, q2, q3,
                      base + OFF_BH + b_base + jj * (16 * TPITCH) + off16);
                bh[2 * jj][0] = q0; bh[2 * jj][1] = q2;
                bh[2 * jj + 1][0] = q1; bh[2 * jj + 1][1] = q3;
            }
#pragma unroll
            for (int i = 0; i < 4; i++)
#pragma unroll
                for (int j = 0; j < 4; j++) {
                    if (F16) mma_hf(acc[i][j], a[i], bh[j]);
                    else     mma_bf(acc[i][j], a[i], bh[j]);
                }
#pragma unroll
            for (int jj = 0; jj < 2; jj++) {
                uint32_t q0, q1, q2, q3;
                LDSM4(q0, q1, q2, q3,
                      base + OFF_BL + b_base + jj * (16 * TPITCH) + off16);
                bl[2 * jj][0] = q0; bl[2 * jj][1] = q2;
                bl[2 * jj + 1][0] = q1; bl[2 * jj + 1][1] = q3;
            }
#pragma unroll
            for (int i = 0; i < 4; i++)
#pragma unroll
                for (int j = 0; j < 4; j++) {
                    if (F16) mma_hf(acc[i][j], a[i], bl[j]);
                    else     mma_bf(acc[i][j], a[i], bl[j]);
                }
            if (!F16) {
#pragma unroll
                for (int i = 0; i < 4; i++)
                    LDSM4(a[i][0], a[i][1], a[i][2], a[i][3],
                          base + TILE_B + a_base + i * (16 * TPITCH) + off16);
#pragma unroll
                for (int i = 0; i < 4; i++)
#pragma unroll
                    for (int j = 0; j < 4; j++) mma_bf(acc[i][j], a[i], bh[j]);
            }
        }
        __syncthreads();
    }

    // epilogue (register-direct)
    int rbase = bm + wm * 64 + (lane >> 2);
    int nbase = bn + wn * 32 + (lane & 3) * 2;
#pragma unroll
    for (int i = 0; i < 4; i++) {
#pragma unroll
        for (int j = 0; j < 4; j++) {
            int n = nbase + j * 8;
#pragma unroll
            for (int h = 0; h < 2; h++) {
                int m = rbase + i * 16 + h * 8;
                float v0 = acc[i][j][2 * h];
                float v1 = acc[i][j][2 * h + 1];
                if (MODE == 0) {
                    __half* Cq = (__half*)Chv;
                    size_t crow = (size_t)m * ldc;
                    float q0 = v0 + aux[n], q1 = v1 + aux[n + 1];
                    __half2 s2; s2.x = __float2half(q0 * q0); s2.y = __float2half(q1 * q1);
                    *(__half2*)(Cq + crow + n) = s2;
                    __half2 qq; qq.x = __float2half(q0); qq.y = __float2half(q1);
                    *(__half2*)(Cq + crow + 512 + n) = qq;
                } else if (MODE == 1) {
                    const float scale = -0.5f / (float)DD;
                    size_t crow = (size_t)m * ldc;
                    float2 o;
                    o.x = scale * (v0 + aux[n]);
                    o.y = scale * (v1 + aux[n + 1]);
                    *(float2*)(Cf + crow + n) = o;
                } else if (MODE == 2) {
                    __half* Ch = (__half*)Chv;
                    __half* Cl = (__half*)Clv;
                    size_t crow = bz * sC + (size_t)m * ldc;
                    float q0 = v0 + aux[n], q1 = v1 + aux[n + 1];
                    __half h0, l0, h1, l1;
                    f16split(q0, h0, l0); f16split(q1, h1, l1);
                    __half2 hh; hh.x = h0; hh.y = h1;
                    __half2 ll; ll.x = l0; ll.y = l1;
                    *(__half2*)(Ch + crow + n) = hh;
                    *(__half2*)(Cl + crow + n) = ll;
                } else {
                    size_t crow = bz * sC + (size_t)m * ldc;
                    float2 o; o.x = v0; o.y = v1;
                    *(float2*)(Cf + crow + n) = o;
                }
            }
        }
    }
}

// ---------------------------------------------------------------------------
// softmax over R: reads fp32 g_z (scaled logits), writes fp16 Fss
// ---------------------------------------------------------------------------
__global__ void softmax_kernel() {
    int row = blockIdx.x;
    int t = threadIdx.x;  // 256
    const float* zrow = g_z + (size_t)row * RR;
    float v0 = zrow[t];
    float v1 = zrow[t + 256];
    float m = fmaxf(v0, v1);
#pragma unroll
    for (int o = 16; o > 0; o >>= 1) m = fmaxf(m, __shfl_xor_sync(0xffffffffu, m, o));
    __shared__ float sm[8];
    __shared__ float ss[8];
    int wid = t >> 5, lid = t & 31;
    if (lid == 0) sm[wid] = m;
    __syncthreads();
    float mm = sm[0];
#pragma unroll
    for (int i = 1; i < 8; i++) mm = fmaxf(mm, sm[i]);
    float e0 = __expf(v0 - mm), e1 = __expf(v1 - mm);
    float s = e0 + e1;
#pragma unroll
    for (int o = 16; o > 0; o >>= 1) s += __shfl_xor_sync(0xffffffffu, s, o);
    if (lid == 0) ss[wid] = s;
    __syncthreads();
    float tot = 0.f;
#pragma unroll
    for (int i = 0; i < 8; i++) tot += ss[i];
    float inv = 1.0f / tot;
    size_t i0 = (size_t)row * RR + t;
    g_fss16[i0] = __float2half(e0 * inv);
    g_fss16[i0 + 256] = __float2half(e1 * inv);
}

// ---------------------------------------------------------------------------
extern "C" void kernel_launch(void* const* d_in, const int* in_sizes, int n_in,
                              void* d_out, int out_size) {
    const float* query   = (const float*)d_in[0];   // (B,L,D)
    const float* Wq      = (const float*)d_in[1];   // (D,D)
    const float* bq      = (const float*)d_in[2];   // (D,)
    const float* Wc      = (const float*)d_in[3];   // (R,L)
    const float* bc      = (const float*)d_in[4];   // (R,)
    const float* centers = (const float*)d_in[5];   // (R,D)
    const float* widths  = (const float*)d_in[6];   // (R,D)
    float* out = (float*)d_out;                     // (B,L,D)

    const int SMEM_BF = 2 * 4 * TILE_B;   // 147456
    const int SMEM_HF = 2 * 3 * TILE_B;   // 110592
    cudaFuncSetAttribute(gemm_s<0, false>, cudaFuncAttributeMaxDynamicSharedMemorySize, SMEM_BF);
    cudaFuncSetAttribute(gemm_s<1, true>,  cudaFuncAttributeMaxDynamicSharedMemorySize, SMEM_HF);
    cudaFuncSetAttribute(gemm_s<2, true>,  cudaFuncAttributeMaxDynamicSharedMemorySize, SMEM_HF);
    cudaFuncSetAttribute(gemm_s<3, true>,  cudaFuncAttributeMaxDynamicSharedMemorySize, SMEM_HF);

    bf16 *qh, *ql, *wqh, *wql;
    __half *qcat16, *bcat16h, *bcat16l;
    __half *qT16, *wc16h, *wc16l, *fss16, *cq16h, *cq16l;
    float *zp, *ccp;
    cudaGetSymbolAddress((void**)&qh, g_query_h);
    cudaGetSymbolAddress((void**)&ql, g_query_l);
    cudaGetSymbolAddress((void**)&wqh, g_wq_h);
    cudaGetSymbolAddress((void**)&wql, g_wq_l);
    cudaGetSymbolAddress((void**)&qcat16, g_qcat16);
    cudaGetSymbolAddress((void**)&bcat16h, g_bcat16h);
    cudaGetSymbolAddress((void**)&bcat16l, g_bcat16l);
    cudaGetSymbolAddress((void**)&qT16, g_qT16);
    cudaGetSymbolAddress((void**)&wc16h, g_wc16h);
    cudaGetSymbolAddress((void**)&wc16l, g_wc16l);
    cudaGetSymbolAddress((void**)&fss16, g_fss16);
    cudaGetSymbolAddress((void**)&cq16h, g_cq16h);
    cudaGetSymbolAddress((void**)&cq16l, g_cq16l);
    cudaGetSymbolAddress((void**)&zp, g_z);
    cudaGetSymbolAddress((void**)&ccp, g_cc);

    // prep: weight splits + query dual-format + rule params
    {
        int n4 = (DD * DD) / 4;
        split_kernel<<<(n4 + 255) / 256, 256>>>(Wq, wqh, wql, n4);
        n4 = (RR * LL) / 4;
        split16_kernel<<<(n4 + 255) / 256, 256>>>(Wc, wc16h, wc16l, n4);
    }
    prep_kernel<<<RR, 128>>>(centers, widths);
    {
        dim3 g(LL / 32, DD / 32, BB);
        dim3 b(32, 8);
        query_prep_kernel<<<g, b>>>(query);
    }

    // G1 (bf16 3-pass): q = query @ Wq^T + bq -> qcat16 = [q^2 | q] fp16
    {
        dim3 g(DD / 128, M1 / 128, 1);
        gemm_s<0, false><<<g, 256, SMEM_BF>>>(
            (const uint16_t*)qh, (const uint16_t*)ql, DD, 0,
            (const uint16_t*)wqh, (const uint16_t*)wql, DD, 0,
            nullptr, qcat16, nullptr, 1024, 0, bq, DD);
    }
    // G2 (fp16 2-pass): z = scale * (qcat16 @ bcat16^T + cc)   (K=1024)
    {
        dim3 g(RR / 128, M1 / 128, 1);
        gemm_s<1, true><<<g, 256, SMEM_HF>>>(
            (const uint16_t*)qcat16, nullptr, 1024, 0,
            (const uint16_t*)bcat16h, (const uint16_t*)bcat16l, 1024, 0,
            zp, nullptr, nullptr, RR, 0, ccp, 1024);
    }
    softmax_kernel<<<M1, 256>>>();
    // G4 (fp16 2-pass): conqT[b] = qT[b] @ Wc^T + bc  (M=D, N=R, K=L)
    {
        dim3 g(RR / 128, DD / 128, BB);
        gemm_s<2, true><<<g, 256, SMEM_HF>>>(
            (const uint16_t*)qT16, nullptr, LL, (size_t)DD * LL,
            (const uint16_t*)wc16h, (const uint16_t*)wc16l, LL, 0,
            nullptr, cq16h, cq16l, RR, (size_t)DD * RR, bc, LL);
    }
    // G5 (fp16 2-pass): out[b] = Fss[b] @ conqT[b]^T  (M=L, N=D, K=R)
    {
        dim3 g(DD / 128, LL / 128, BB);
        gemm_s<3, true><<<g, 256, SMEM_HF>>>(
            (const uint16_t*)fss16, nullptr, RR, (size_t)LL * RR,
            (const uint16_t*)cq16h, (const uint16_t*)cq16l, RR, (size_t)DD * RR,
            out, nullptr, nullptr, DD, (size_t)LL * DD, nullptr, RR);
    }
}

// round 13
// speedup vs baseline: 1.6097x; 1.1563x over previous
#include <cuda_runtime.h>
#include <cuda_bf16.h>
#include <cuda_fp16.h>
#include <cstdint>

// Problem constants
#define BB 8
#define LL 2048
#define DD 512
#define RR 512
#define M1 (BB * LL)   // 16384 flattened (B,L)

typedef __nv_bfloat16 bf16;
typedef __nv_bfloat162 bf162;

__device__ __forceinline__ uint32_t smem_to_u32(const void* smem_ptr) {
    uint32_t addr;
    asm("{ .reg .u64 tmp; cvta.to.shared.u64 tmp, %1; cvt.u32.u64 %0, tmp; }"
        : "=r"(addr) : "l"(smem_ptr));
    return addr;
}

__device__ __forceinline__ void bf16split(float x, bf16& h, bf16& l) {
    h = __float2bfloat16(x);
    l = __float2bfloat16(x - __bfloat162float(h));
}

__device__ __forceinline__ void f16split(float x, __half& h, __half& l) {
    h = __float2half(x);
    l = __float2half(x - __half2float(h));
}

#define CPASYNC16(dst, src) \
    asm volatile("cp.async.cg.shared.global [%0], [%1], 16;" :: "r"(dst), "l"(src))
#define CPASYNC_COMMIT() asm volatile("cp.async.commit_group;" ::: "memory")

#define LDSM4(r0, r1, r2, r3, addr) \
    asm volatile("ldmatrix.sync.aligned.m8n8.x4.shared.b16 {%0,%1,%2,%3}, [%4];" \
                 : "=r"(r0), "=r"(r1), "=r"(r2), "=r"(r3) : "r"(addr))

__device__ __forceinline__ void mma_bf(float* c, const uint32_t* a, const uint32_t* b) {
    asm volatile("mma.sync.aligned.m16n8k16.row.col.f32.bf16.bf16.f32 "
                 "{%0,%1,%2,%3}, {%4,%5,%6,%7}, {%8,%9}, {%0,%1,%2,%3};"
                 : "+f"(c[0]), "+f"(c[1]), "+f"(c[2]), "+f"(c[3])
                 : "r"(a[0]), "r"(a[1]), "r"(a[2]), "r"(a[3]),
                   "r"(b[0]), "r"(b[1]));
}
__device__ __forceinline__ void mma_hf(float* c, const uint32_t* a, const uint32_t* b) {
    asm volatile("mma.sync.aligned.m16n8k16.row.col.f32.f16.f16.f32 "
                 "{%0,%1,%2,%3}, {%4,%5,%6,%7}, {%8,%9}, {%0,%1,%2,%3};"
                 : "+f"(c[0]), "+f"(c[1]), "+f"(c[2]), "+f"(c[3])
                 : "r"(a[0]), "r"(a[1]), "r"(a[2]), "r"(a[3]),
                   "r"(b[0]), "r"(b[1]));
}

// ---------------- scratch (device globals; no allocation allowed) ----------
__device__ bf16   g_query_h[(size_t)M1 * DD];
__device__ bf16   g_query_l[(size_t)M1 * DD];
__device__ bf16   g_wq_h[DD * DD];
__device__ bf16   g_wq_l[DD * DD];
__device__ __half g_qcat16[(size_t)M1 * 1024];   // [q^2 | q], fp16 single
__device__ __half g_bcat16h[RR * 1024];          // [invw2 | -2c*invw2] fp16 split
__device__ __half g_bcat16l[RR * 1024];
__device__ float  g_z[(size_t)M1 * RR];
__device__ float  g_cc[RR];
// fp16 single path (G4/G5)
__device__ __half g_qT16[(size_t)BB * DD * LL];  // transposed query
__device__ __half g_wc16[RR * LL];
__device__ __half g_fss16[(size_t)M1 * RR];
__device__ __half g_cq16[(size_t)BB * DD * RR];  // conqT

// ---------------------------------------------------------------------------
// split: fp32 -> (hi, lo) bf16 (for Wq)
// ---------------------------------------------------------------------------
__global__ void split_kernel(const float* __restrict__ src, bf16* __restrict__ hi,
                             bf16* __restrict__ lo, int n4) {
    int i = blockIdx.x * blockDim.x + threadIdx.x;
    if (i >= n4) return;
    float4 v = ((const float4*)src)[i];
    bf16 h0, l0, h1, l1, h2, l2, h3, l3;
    bf16split(v.x, h0, l0); bf16split(v.y, h1, l1);
    bf16split(v.z, h2, l2); bf16split(v.w, h3, l3);
    bf162 hh0; hh0.x = h0; hh0.y = h1;
    bf162 hh1; hh1.x = h2; hh1.y = h3;
    bf162 ll0; ll0.x = l0; ll0.y = l1;
    bf162 ll1; ll1.x = l2; ll1.y = l3;
    ((bf162*)hi)[i * 2 + 0] = hh0;
    ((bf162*)hi)[i * 2 + 1] = hh1;
    ((bf162*)lo)[i * 2 + 0] = ll0;
    ((bf162*)lo)[i * 2 + 1] = ll1;
}

// ---------------------------------------------------------------------------
// tofp16: fp32 -> fp16 single (for Wc)
// ---------------------------------------------------------------------------
__global__ void tofp16_kernel(const float* __restrict__ src, __half* __restrict__ dst,
                              int n4) {
    int i = blockIdx.x * blockDim.x + threadIdx.x;
    if (i >= n4) return;
    float4 v = ((const float4*)src)[i];
    __half2 a0; a0.x = __float2half(v.x); a0.y = __float2half(v.y);
    __half2 a1; a1.x = __float2half(v.z); a1.y = __float2half(v.w);
    ((__half2*)dst)[i * 2 + 0] = a0;
    ((__half2*)dst)[i * 2 + 1] = a1;
}

// ---------------------------------------------------------------------------
// query prep: single read -> row-major bf16 split (G1) + transposed fp16 (G4)
// ---------------------------------------------------------------------------
__global__ void query_prep_kernel(const float* __restrict__ query) {
    __shared__ float tile[32][33];
    int b = blockIdx.z;
    int l0 = blockIdx.x * 32, d0 = blockIdx.y * 32;
    int tx = threadIdx.x, ty = threadIdx.y;
    const float* src = query + (size_t)b * LL * DD;
#pragma unroll
    for (int i = 0; i < 4; i++) {
        int l = l0 + ty + 8 * i;
        float v = src[(size_t)l * DD + d0 + tx];
        tile[ty + 8 * i][tx] = v;
        bf16 h, lw;
        bf16split(v, h, lw);
        size_t idx = (size_t)(b * LL + l) * DD + d0 + tx;
        g_query_h[idx] = h;
        g_query_l[idx] = lw;
    }
    __syncthreads();
    size_t base = (size_t)b * DD * LL;
#pragma unroll
    for (int i = 0; i < 4; i++) {
        float v = tile[tx][ty + 8 * i];
        size_t idx = base + (size_t)(d0 + ty + 8 * i) * LL + l0 + tx;
        g_qT16[idx] = __float2half(v);
    }
}

// ---------------------------------------------------------------------------
// prep: bcat = [invw2 | -2c*invw2] fp16 split, cc[r] = sum c^2*invw2
// ---------------------------------------------------------------------------
__global__ void prep_kernel(const float* __restrict__ centers,
                            const float* __restrict__ widths) {
    int r = blockIdx.x;
    int t = threadIdx.x;  // 128
    float acc = 0.f;
    for (int d = t; d < DD; d += 128) {
        float w = widths[r * DD + d];
        float c = centers[r * DD + d];
        float iw = 1.0f / (w * w);
        float b2 = -2.0f * c * iw;
        __half h, l;
        f16split(iw, h, l);
        g_bcat16h[r * 1024 + d] = h;
        g_bcat16l[r * 1024 + d] = l;
        f16split(b2, h, l);
        g_bcat16h[r * 1024 + 512 + d] = h;
        g_bcat16l[r * 1024 + 512 + d] = l;
        acc += c * c * iw;
    }
    __shared__ float sred[128];
    sred[t] = acc;
    __syncthreads();
    for (int s = 64; s > 0; s >>= 1) {
        if (t < s) sred[t] += sred[t + s];
        __syncthreads();
    }
    if (t == 0) g_cc[r] = sred[0];
}

// ---------------------------------------------------------------------------
// Split-precision NT GEMM via mma.sync m16n8k16.
//   KIND 0: bf16 3-pass (AhBh + AhBl + AlBh), 4 tiles/stage.
//   KIND 1: fp16 2-pass (A·Bh + A·Bl), A single, 3 tiles/stage.
//   KIND 2: fp16 1-pass (A·B), both single, 2 tiles/stage.
// 128x128 CTA tile, 8 warps of 64x32. K-chunk 64, 2-stage cp.async pipeline.
// SMEM tile: 128 rows x 128B data, 144B pitch (conflict-free ldmatrix+store).
// MODE 0: qcat ((v+aux)^2 | (v+aux)) -> single fp16 (Chv; ldc=1024)
// MODE 1: fp32 scale*(v+aux[n]) -> Cf
// MODE 2: fp16 single v+aux[n]  -> Chv (as __half*)
// MODE 3: fp32 raw              -> Cf
// ---------------------------------------------------------------------------
#define TPITCH 144
#define TILE_B (128 * TPITCH)        // 18432

template <int MODE, int KIND>
__global__ __launch_bounds__(256, 1) void gemm_s(
    const uint16_t* __restrict__ Ah, const uint16_t* __restrict__ Al, int lda, size_t sA,
    const uint16_t* __restrict__ Bh, const uint16_t* __restrict__ Bl, int ldb, size_t sB,
    float* __restrict__ Cf, void* __restrict__ Chv,
    int ldc, size_t sC, const float* __restrict__ aux, int K) {
    constexpr uint32_t NT_ = (KIND == 0) ? 4u : (KIND == 1) ? 3u : 2u;
    constexpr uint32_t STB = NT_ * TILE_B;
    constexpr uint32_t OFF_BH = (KIND == 0) ? 2 * TILE_B : TILE_B;
    constexpr uint32_t OFF_BL = OFF_BH + TILE_B;   // valid only for KIND<=1
    extern __shared__ char smem[];
    uint32_t sb = smem_to_u32(smem);
    int t = threadIdx.x;
    int lane = t & 31, wid = t >> 5;
    int wm = wid & 1, wn = wid >> 1;
    int bn = blockIdx.x * 128, bm = blockIdx.y * 128;
    size_t bz = blockIdx.z;
    Ah += bz * sA;
    Bh += bz * sB;
    const uint16_t* AlB = (KIND == 0) ? (Al + bz * sA) : Ah;
    const uint16_t* BlB = (KIND <= 1) ? (Bl + bz * sB) : Bh;

    // cp.async plan: each thread covers rows r0+32i, one 16B column, per tile.
    int r0 = t >> 3;
    int cc = t & 7;
    const uint16_t* gA_h = Ah + (size_t)(bm + r0) * lda + cc * 8;
    const uint16_t* gA_l = AlB + (size_t)(bm + r0) * lda + cc * 8;
    const uint16_t* gB_h = Bh + (size_t)(bn + r0) * ldb + cc * 8;
    const uint16_t* gB_l = BlB + (size_t)(bn + r0) * ldb + cc * 8;
    uint32_t soff = (uint32_t)(r0 * TPITCH + cc * 16);

    float acc[4][4][4] = {};
    const int nk = K >> 6;

    // prologue: chunk 0 -> stage 0
    {
        uint32_t db = sb;
#pragma unroll
        for (int i = 0; i < 4; i++) {
            uint32_t o = soff + (uint32_t)(i * 32 * TPITCH);
            size_t ga = (size_t)(32 * i) * lda;
            size_t gb = (size_t)(32 * i) * ldb;
            CPASYNC16(db + o, gA_h + ga);
            if (KIND == 0) CPASYNC16(db + TILE_B + o, gA_l + ga);
            CPASYNC16(db + OFF_BH + o, gB_h + gb);
            if (KIND <= 1) CPASYNC16(db + OFF_BL + o, gB_l + gb);
        }
        CPASYNC_COMMIT();
    }

    int lm = lane & 15, lq = lane >> 4;
    uint32_t a_base = (uint32_t)((wm * 64 + lm) * TPITCH);
    uint32_t b_base = (uint32_t)((wn * 32 + lm) * TPITCH);

    for (int kt = 0; kt < nk; kt++) {
        int buf = kt & 1;
        if (kt + 1 < nk) {
            uint32_t db = sb + (buf ^ 1) * STB;
            int koff = (kt + 1) * 64;
#pragma unroll
            for (int i = 0; i < 4; i++) {
                uint32_t o = soff + (uint32_t)(i * 32 * TPITCH);
                size_t ga = (size_t)(32 * i) * lda + koff;
                size_t gb = (size_t)(32 * i) * ldb + koff;
                CPASYNC16(db + o, gA_h + ga);
                if (KIND == 0) CPASYNC16(db + TILE_B + o, gA_l + ga);
                CPASYNC16(db + OFF_BH + o, gB_h + gb);
                if (KIND <= 1) CPASYNC16(db + OFF_BL + o, gB_l + gb);
            }
            CPASYNC_COMMIT();
            asm volatile("cp.async.wait_group 1;" ::: "memory");
        } else {
            asm volatile("cp.async.wait_group 0;" ::: "memory");
        }
        __syncthreads();
        uint32_t base = sb + buf * STB;
#pragma unroll
        for (int ks = 0; ks < 4; ks++) {
            uint32_t off16 = (uint32_t)((2 * ks + lq) * 16);
            uint32_t a[4][4], bh[4][2], bl[4][2];
#pragma unroll
            for (int i = 0; i < 4; i++)
                LDSM4(a[i][0], a[i][1], a[i][2], a[i][3],
                      base + a_base + i * (16 * TPITCH) + off16);
#pragma unroll
            for (int jj = 0; jj < 2; jj++) {
                uint32_t q0, q1, q2, q3;
                LDSM4(q0, q1, q2, q3,
                      base + OFF_BH + b_base + jj * (16 * TPITCH) + off16);
                bh[2 * jj][0] = q0; bh[2 * jj][1] = q2;
                bh[2 * jj + 1][0] = q1; bh[2 * jj + 1][1] = q3;
            }
#pragma unroll
            for (int i = 0; i < 4; i++)
#pragma unroll
                for (int j = 0; j < 4; j++) {
                    if (KIND == 0) mma_bf(acc[i][j], a[i], bh[j]);
                    else           mma_hf(acc[i][j], a[i], bh[j]);
                }
            if (KIND <= 1) {
#pragma unroll
                for (int jj = 0; jj < 2; jj++) {
                    uint32_t q0, q1, q2, q3;
                    LDSM4(q0, q1, q2, q3,
                          base + OFF_BL + b_base + jj * (16 * TPITCH) + off16);
                    bl[2 * jj][0] = q0; bl[2 * jj][1] = q2;
                    bl[2 * jj + 1][0] = q1; bl[2 * jj + 1][1] = q3;
                }
#pragma unroll
                for (int i = 0; i < 4; i++)
#pragma unroll
                    for (int j = 0; j < 4; j++) {
                        if (KIND == 0) mma_bf(acc[i][j], a[i], bl[j]);
                        else           mma_hf(acc[i][j], a[i], bl[j]);
                    }
            }
            if (KIND == 0) {
#pragma unroll
                for (int i = 0; i < 4; i++)
                    LDSM4(a[i][0], a[i][1], a[i][2], a[i][3],
                          base + TILE_B + a_base + i * (16 * TPITCH) + off16);
#pragma unroll
                for (int i = 0; i < 4; i++)
#pragma unroll
                    for (int j = 0; j < 4; j++) mma_bf(acc[i][j], a[i], bh[j]);
            }
        }
        __syncthreads();
    }

    // epilogue (register-direct)
    int rbase = bm + wm * 64 + (lane >> 2);
    int nbase = bn + wn * 32 + (lane & 3) * 2;
#pragma unroll
    for (int i = 0; i < 4; i++) {
#pragma unroll
        for (int j = 0; j < 4; j++) {
            int n = nbase + j * 8;
#pragma unroll
            for (int h = 0; h < 2; h++) {
                int m = rbase + i * 16 + h * 8;
                float v0 = acc[i][j][2 * h];
                float v1 = acc[i][j][2 * h + 1];
                if (MODE == 0) {
                    __half* Cq = (__half*)Chv;
                    size_t crow = (size_t)m * ldc;
                    float q0 = v0 + aux[n], q1 = v1 + aux[n + 1];
                    __half2 s2; s2.x = __float2half(q0 * q0); s2.y = __float2half(q1 * q1);
                    *(__half2*)(Cq + crow + n) = s2;
                    __half2 qq; qq.x = __float2half(q0); qq.y = __float2half(q1);
                    *(__half2*)(Cq + crow + 512 + n) = qq;
                } else if (MODE == 1) {
                    const float scale = -0.5f / (float)DD;
                    size_t crow = (size_t)m * ldc;
                    float2 o;
                    o.x = scale * (v0 + aux[n]);
                    o.y = scale * (v1 + aux[n + 1]);
                    *(float2*)(Cf + crow + n) = o;
                } else if (MODE == 2) {
                    __half* Ch = (__half*)Chv;
                    size_t crow = bz * sC + (size_t)m * ldc;
                    float q0 = v0 + aux[n], q1 = v1 + aux[n + 1];
                    __half2 hh; hh.x = __float2half(q0); hh.y = __float2half(q1);
                    *(__half2*)(Ch + crow + n) = hh;
                } else {
                    size_t crow = bz * sC + (size_t)m * ldc;
                    float2 o; o.x = v0; o.y = v1;
                    *(float2*)(Cf + crow + n) = o;
                }
            }
        }
    }
}

// ---------------------------------------------------------------------------
// softmax over R: reads fp32 g_z (scaled logits), writes fp16 Fss
// ---------------------------------------------------------------------------
__global__ void softmax_kernel() {
    int row = blockIdx.x;
    int t = threadIdx.x;  // 256
    const float* zrow = g_z + (size_t)row * RR;
    float v0 = zrow[t];
    float v1 = zrow[t + 256];
    float m = fmaxf(v0, v1);
#pragma unroll
    for (int o = 16; o > 0; o >>= 1) m = fmaxf(m, __shfl_xor_sync(0xffffffffu, m, o));
    __shared__ float sm[8];
    __shared__ float ss[8];
    int wid = t >> 5, lid = t & 31;
    if (lid == 0) sm[wid] = m;
    __syncthreads();
    float mm = sm[0];
#pragma unroll
    for (int i = 1; i < 8; i++) mm = fmaxf(mm, sm[i]);
    float e0 = __expf(v0 - mm), e1 = __expf(v1 - mm);
    float s = e0 + e1;
#pragma unroll
    for (int o = 16; o > 0; o >>= 1) s += __shfl_xor_sync(0xffffffffu, s, o);
    if (lid == 0) ss[wid] = s;
    __syncthreads();
    float tot = 0.f;
#pragma unroll
    for (int i = 0; i < 8; i++) tot += ss[i];
    float inv = 1.0f / tot;
    size_t i0 = (size_t)row * RR + t;
    g_fss16[i0] = __float2half(e0 * inv);
    g_fss16[i0 + 256] = __float2half(e1 * inv);
}

// ---------------------------------------------------------------------------
extern "C" void kernel_launch(void* const* d_in, const int* in_sizes, int n_in,
                              void* d_out, int out_size) {
    const float* query   = (const float*)d_in[0];   // (B,L,D)
    const float* Wq      = (const float*)d_in[1];   // (D,D)
    const float* bq      = (const float*)d_in[2];   // (D,)
    const float* Wc      = (const float*)d_in[3];   // (R,L)
    const float* bc      = (const float*)d_in[4];   // (R,)
    const float* centers = (const float*)d_in[5];   // (R,D)
    const float* widths  = (const float*)d_in[6];   // (R,D)
    float* out = (float*)d_out;                     // (B,L,D)

    const int SMEM_K0 = 2 * 4 * TILE_B;   // 147456
    const int SMEM_K1 = 2 * 3 * TILE_B;   // 110592
    const int SMEM_K2 = 2 * 2 * TILE_B;   // 73728
    cudaFuncSetAttribute(gemm_s<0, 0>, cudaFuncAttributeMaxDynamicSharedMemorySize, SMEM_K0);
    cudaFuncSetAttribute(gemm_s<1, 1>, cudaFuncAttributeMaxDynamicSharedMemorySize, SMEM_K1);
    cudaFuncSetAttribute(gemm_s<2, 2>, cudaFuncAttributeMaxDynamicSharedMemorySize, SMEM_K2);
    cudaFuncSetAttribute(gemm_s<3, 2>, cudaFuncAttributeMaxDynamicSharedMemorySize, SMEM_K2);

    bf16 *qh, *ql, *wqh, *wql;
    __half *qcat16, *bcat16h, *bcat16l;
    __half *qT16, *wc16, *fss16, *cq16;
    float *zp, *ccp;
    cudaGetSymbolAddress((void**)&qh, g_query_h);
    cudaGetSymbolAddress((void**)&ql, g_query_l);
    cudaGetSymbolAddress((void**)&wqh, g_wq_h);
    cudaGetSymbolAddress((void**)&wql, g_wq_l);
    cudaGetSymbolAddress((void**)&qcat16, g_qcat16);
    cudaGetSymbolAddress((void**)&bcat16h, g_bcat16h);
    cudaGetSymbolAddress((void**)&bcat16l, g_bcat16l);
    cudaGetSymbolAddress((void**)&qT16, g_qT16);
    cudaGetSymbolAddress((void**)&wc16, g_wc16);
    cudaGetSymbolAddress((void**)&fss16, g_fss16);
    cudaGetSymbolAddress((void**)&cq16, g_cq16);
    cudaGetSymbolAddress((void**)&zp, g_z);
    cudaGetSymbolAddress((void**)&ccp, g_cc);

    // prep: weight conversions + query dual-format + rule params
    {
        int n4 = (DD * DD) / 4;
        split_kernel<<<(n4 + 255) / 256, 256>>>(Wq, wqh, wql, n4);
        n4 = (RR * LL) / 4;
        tofp16_kernel<<<(n4 + 255) / 256, 256>>>(Wc, wc16, n4);
    }
    prep_kernel<<<RR, 128>>>(centers, widths);
    {
        dim3 g(LL / 32, DD / 32, BB);
        dim3 b(32, 8);
        query_prep_kernel<<<g, b>>>(query);
    }

    // G1 (bf16 3-pass): q = query @ Wq^T + bq -> qcat16 = [q^2 | q] fp16
    {
        dim3 g(DD / 128, M1 / 128, 1);
        gemm_s<0, 0><<<g, 256, SMEM_K0>>>(
            (const uint16_t*)qh, (const uint16_t*)ql, DD, 0,
            (const uint16_t*)wqh, (const uint16_t*)wql, DD, 0,
            nullptr, qcat16, 1024, 0, bq, DD);
    }
    // G2 (fp16 2-pass): z = scale * (qcat16 @ bcat16^T + cc)   (K=1024)
    {
        dim3 g(RR / 128, M1 / 128, 1);
        gemm_s<1, 1><<<g, 256, SMEM_K1>>>(
            (const uint16_t*)qcat16, nullptr, 1024, 0,
            (const uint16_t*)bcat16h, (const uint16_t*)bcat16l, 1024, 0,
            zp, nullptr, RR, 0, ccp, 1024);
    }
    softmax_kernel<<<M1, 256>>>();
    // G4 (fp16 1-pass): conqT[b] = qT[b] @ Wc^T + bc  (M=D, N=R, K=L)
    {
        dim3 g(RR / 128, DD / 128, BB);
        gemm_s<2, 2><<<g, 256, SMEM_K2>>>(
            (const uint16_t*)qT16, nullptr, LL, (size_t)DD * LL,
            (const uint16_t*)wc16, nullptr, LL, 0,
            nullptr, cq16, RR, (size_t)DD * RR, bc, LL);
    }
    // G5 (fp16 1-pass): out[b] = Fss[b] @ conqT[b]^T  (M=L, N=D, K=R)
    {
        dim3 g(DD / 128, LL / 128, BB);
        gemm_s<3, 2><<<g, 256, SMEM_K2>>>(
            (const uint16_t*)fss16, nullptr, RR, (size_t)LL * RR,
            (const uint16_t*)cq16, nullptr, RR, (size_t)DD * RR,
            out, nullptr, DD, (size_t)LL * DD, nullptr, RR);
    }
}

// round 14
// speedup vs baseline: 2.1667x; 1.3460x over previous
#include <cuda_runtime.h>
#include <cuda_bf16.h>
#include <cuda_fp16.h>
#include <cstdint>

// Problem constants
#define BB 8
#define LL 2048
#define DD 512
#define RR 512
#define M1 (BB * LL)   // 16384 flattened (B,L)

__device__ __forceinline__ uint32_t smem_to_u32(const void* smem_ptr) {
    uint32_t addr;
    asm("{ .reg .u64 tmp; cvta.to.shared.u64 tmp, %1; cvt.u32.u64 %0, tmp; }"
        : "=r"(addr) : "l"(smem_ptr));
    return addr;
}

__device__ __forceinline__ void f16split(float x, __half& h, __half& l) {
    h = __float2half(x);
    l = __float2half(x - __half2float(h));
}

#define CPASYNC16(dst, src) \
    asm volatile("cp.async.cg.shared.global [%0], [%1], 16;" :: "r"(dst), "l"(src))
#define CPASYNC_COMMIT() asm volatile("cp.async.commit_group;" ::: "memory")

#define LDSM4(r0, r1, r2, r3, addr) \
    asm volatile("ldmatrix.sync.aligned.m8n8.x4.shared.b16 {%0,%1,%2,%3}, [%4];" \
                 : "=r"(r0), "=r"(r1), "=r"(r2), "=r"(r3) : "r"(addr))

__device__ __forceinline__ void mma_hf(float* c, const uint32_t* a, const uint32_t* b) {
    asm volatile("mma.sync.aligned.m16n8k16.row.col.f32.f16.f16.f32 "
                 "{%0,%1,%2,%3}, {%4,%5,%6,%7}, {%8,%9}, {%0,%1,%2,%3};"
                 : "+f"(c[0]), "+f"(c[1]), "+f"(c[2]), "+f"(c[3])
                 : "r"(a[0]), "r"(a[1]), "r"(a[2]), "r"(a[3]),
                   "r"(b[0]), "r"(b[1]));
}

// ---------------- scratch (device globals; no allocation allowed) ----------
__device__ __half g_q16[(size_t)M1 * DD];        // query row-major fp16
__device__ __half g_wq16h[DD * DD];              // Wq fp16 split
__device__ __half g_wq16l[DD * DD];
__device__ __half g_qcat16[(size_t)M1 * 1024];   // [q^2 | q], fp16 single
__device__ __half g_bcat16[RR * 1024];           // [invw2 | -2c*invw2] fp16
__device__ float  g_z[(size_t)M1 * RR];
__device__ float  g_cc[RR];
__device__ __half g_qT16[(size_t)BB * DD * LL];  // transposed query
__device__ __half g_wc16[RR * LL];
__device__ __half g_fss16[(size_t)M1 * RR];
__device__ __half g_cq16[(size_t)BB * DD * RR];  // conqT

// ---------------------------------------------------------------------------
// split16: fp32 -> (hi, lo) fp16 (for Wq)
// ---------------------------------------------------------------------------
__global__ void split16_kernel(const float* __restrict__ src, __half* __restrict__ hi,
                               __half* __restrict__ lo, int n4) {
    int i = blockIdx.x * blockDim.x + threadIdx.x;
    if (i >= n4) return;
    float4 v = ((const float4*)src)[i];
    __half h0, l0, h1, l1, h2, l2, h3, l3;
    f16split(v.x, h0, l0); f16split(v.y, h1, l1);
    f16split(v.z, h2, l2); f16split(v.w, h3, l3);
    __half2 a0; a0.x = h0; a0.y = h1;
    __half2 a1; a1.x = h2; a1.y = h3;
    __half2 b0; b0.x = l0; b0.y = l1;
    __half2 b1; b1.x = l2; b1.y = l3;
    ((__half2*)hi)[i * 2 + 0] = a0;
    ((__half2*)hi)[i * 2 + 1] = a1;
    ((__half2*)lo)[i * 2 + 0] = b0;
    ((__half2*)lo)[i * 2 + 1] = b1;
}

// ---------------------------------------------------------------------------
// tofp16: fp32 -> fp16 single (for Wc)
// ---------------------------------------------------------------------------
__global__ void tofp16_kernel(const float* __restrict__ src, __half* __restrict__ dst,
                              int n4) {
    int i = blockIdx.x * blockDim.x + threadIdx.x;
    if (i >= n4) return;
    float4 v = ((const float4*)src)[i];
    __half2 a0; a0.x = __float2half(v.x); a0.y = __float2half(v.y);
    __half2 a1; a1.x = __float2half(v.z); a1.y = __float2half(v.w);
    ((__half2*)dst)[i * 2 + 0] = a0;
    ((__half2*)dst)[i * 2 + 1] = a1;
}

// ---------------------------------------------------------------------------
// query prep: single read -> row-major fp16 (G1) + transposed fp16 (G4)
// ---------------------------------------------------------------------------
__global__ void query_prep_kernel(const float* __restrict__ query) {
    __shared__ float tile[32][33];
    int b = blockIdx.z;
    int l0 = blockIdx.x * 32, d0 = blockIdx.y * 32;
    int tx = threadIdx.x, ty = threadIdx.y;
    const float* src = query + (size_t)b * LL * DD;
#pragma unroll
    for (int i = 0; i < 4; i++) {
        int l = l0 + ty + 8 * i;
        float v = src[(size_t)l * DD + d0 + tx];
        tile[ty + 8 * i][tx] = v;
        size_t idx = (size_t)(b * LL + l) * DD + d0 + tx;
        g_q16[idx] = __float2half(v);
    }
    __syncthreads();
    size_t base = (size_t)b * DD * LL;
#pragma unroll
    for (int i = 0; i < 4; i++) {
        float v = tile[tx][ty + 8 * i];
        size_t idx = base + (size_t)(d0 + ty + 8 * i) * LL + l0 + tx;
        g_qT16[idx] = __float2half(v);
    }
}

// ---------------------------------------------------------------------------
// prep: bcat = [invw2 | -2c*invw2] fp16 single, cc[r] = sum c^2*invw2
// ---------------------------------------------------------------------------
__global__ void prep_kernel(const float* __restrict__ centers,
                            const float* __restrict__ widths) {
    int r = blockIdx.x;
    int t = threadIdx.x;  // 128
    float acc = 0.f;
    for (int d = t; d < DD; d += 128) {
        float w = widths[r * DD + d];
        float c = centers[r * DD + d];
        float iw = 1.0f / (w * w);
        float b2 = -2.0f * c * iw;
        g_bcat16[r * 1024 + d] = __float2half(iw);
        g_bcat16[r * 1024 + 512 + d] = __float2half(b2);
        acc += c * c * iw;
    }
    __shared__ float sred[128];
    sred[t] = acc;
    __syncthreads();
    for (int s = 64; s > 0; s >>= 1) {
        if (t < s) sred[t] += sred[t + s];
        __syncthreads();
    }
    if (t == 0) g_cc[r] = sred[0];
}

// ---------------------------------------------------------------------------
// fp16 NT GEMM via mma.sync m16n8k16.
//   KIND 1: fp16 2-pass (A·Bh + A·Bl), A single, 3 tiles/stage.
//   KIND 2: fp16 1-pass (A·B), both single, 2 tiles/stage.
// 128x128 CTA tile, 8 warps of 64x32. K-chunk 64, 2-stage cp.async pipeline.
// SMEM tile: 128 rows x 128B data, 144B pitch (conflict-free ldmatrix+store).
// MODE 0: qcat ((v+aux)^2 | (v+aux)) -> single fp16 (Chv; ldc=1024)
// MODE 1: fp32 scale*(v+aux[n]) -> Cf
// MODE 2: fp16 single v+aux[n]  -> Chv (as __half*)
// MODE 3: fp32 raw              -> Cf
// ---------------------------------------------------------------------------
#define TPITCH 144
#define TILE_B (128 * TPITCH)        // 18432

template <int MODE, int KIND>
__global__ __launch_bounds__(256, 1) void gemm_s(
    const uint16_t* __restrict__ Ah, int lda, size_t sA,
    const uint16_t* __restrict__ Bh, const uint16_t* __restrict__ Bl, int ldb, size_t sB,
    float* __restrict__ Cf, void* __restrict__ Chv,
    int ldc, size_t sC, const float* __restrict__ aux, int K) {
    constexpr uint32_t NT_ = (KIND == 1) ? 3u : 2u;
    constexpr uint32_t STB = NT_ * TILE_B;
    constexpr uint32_t OFF_BH = TILE_B;
    constexpr uint32_t OFF_BL = 2 * TILE_B;   // valid only for KIND==1
    extern __shared__ char smem[];
    uint32_t sb = smem_to_u32(smem);
    int t = threadIdx.x;
    int lane = t & 31, wid = t >> 5;
    int wm = wid & 1, wn = wid >> 1;
    int bn = blockIdx.x * 128, bm = blockIdx.y * 128;
    size_t bz = blockIdx.z;
    Ah += bz * sA;
    Bh += bz * sB;
    const uint16_t* BlB = (KIND == 1) ? (Bl + bz * sB) : Bh;

    // cp.async plan: each thread covers rows r0+32i, one 16B column, per tile.
    int r0 = t >> 3;
    int cc = t & 7;
    const uint16_t* gA_h = Ah + (size_t)(bm + r0) * lda + cc * 8;
    const uint16_t* gB_h = Bh + (size_t)(bn + r0) * ldb + cc * 8;
    const uint16_t* gB_l = BlB + (size_t)(bn + r0) * ldb + cc * 8;
    uint32_t soff = (uint32_t)(r0 * TPITCH + cc * 16);

    float acc[4][4][4] = {};
    const int nk = K >> 6;

    // prologue: chunk 0 -> stage 0
    {
        uint32_t db = sb;
#pragma unroll
        for (int i = 0; i < 4; i++) {
            uint32_t o = soff + (uint32_t)(i * 32 * TPITCH);
            size_t ga = (size_t)(32 * i) * lda;
            size_t gb = (size_t)(32 * i) * ldb;
            CPASYNC16(db + o, gA_h + ga);
            CPASYNC16(db + OFF_BH + o, gB_h + gb);
            if (KIND == 1) CPASYNC16(db + OFF_BL + o, gB_l + gb);
        }
        CPASYNC_COMMIT();
    }

    int lm = lane & 15, lq = lane >> 4;
    uint32_t a_base = (uint32_t)((wm * 64 + lm) * TPITCH);
    uint32_t b_base = (uint32_t)((wn * 32 + lm) * TPITCH);

    for (int kt = 0; kt < nk; kt++) {
        int buf = kt & 1;
        if (kt + 1 < nk) {
            uint32_t db = sb + (buf ^ 1) * STB;
            int koff = (kt + 1) * 64;
#pragma unroll
            for (int i = 0; i < 4; i++) {
                uint32_t o = soff + (uint32_t)(i * 32 * TPITCH);
                size_t ga = (size_t)(32 * i) * lda + koff;
                size_t gb = (size_t)(32 * i) * ldb + koff;
                CPASYNC16(db + o, gA_h + ga);
                CPASYNC16(db + OFF_BH + o, gB_h + gb);
                if (KIND == 1) CPASYNC16(db + OFF_BL + o, gB_l + gb);
            }
            CPASYNC_COMMIT();
            asm volatile("cp.async.wait_group 1;" ::: "memory");
        } else {
            asm volatile("cp.async.wait_group 0;" ::: "memory");
        }
        __syncthreads();
        uint32_t base = sb + buf * STB;
#pragma unroll
        for (int ks = 0; ks < 4; ks++) {
            uint32_t off16 = (uint32_t)((2 * ks + lq) * 16);
            uint32_t a[4][4], bh[4][2], bl[4][2];
#pragma unroll
            for (int i = 0; i < 4; i++)
                LDSM4(a[i][0], a[i][1], a[i][2], a[i][3],
                      base + a_base + i * (16 * TPITCH) + off16);
#pragma unroll
            for (int jj = 0; jj < 2; jj++) {
                uint32_t q0, q1, q2, q3;
                LDSM4(q0, q1, q2, q3,
                      base + OFF_BH + b_base + jj * (16 * TPITCH) + off16);
                bh[2 * jj][0] = q0; bh[2 * jj][1] = q2;
                bh[2 * jj + 1][0] = q1; bh[2 * jj + 1][1] = q3;
            }
#pragma unroll
            for (int i = 0; i < 4; i++)
#pragma unroll
                for (int j = 0; j < 4; j++) mma_hf(acc[i][j], a[i], bh[j]);
            if (KIND == 1) {
#pragma unroll
                for (int jj = 0; jj < 2; jj++) {
                    uint32_t q0, q1, q2, q3;
                    LDSM4(q0, q1, q2, q3,
                          base + OFF_BL + b_base + jj * (16 * TPITCH) + off16);
                    bl[2 * jj][0] = q0; bl[2 * jj][1] = q2;
                    bl[2 * jj + 1][0] = q1; bl[2 * jj + 1][1] = q3;
                }
#pragma unroll
                for (int i = 0; i < 4; i++)
#pragma unroll
                    for (int j = 0; j < 4; j++) mma_hf(acc[i][j], a[i], bl[j]);
            }
        }
        __syncthreads();
    }

    // epilogue (register-direct)
    int rbase = bm + wm * 64 + (lane >> 2);
    int nbase = bn + wn * 32 + (lane & 3) * 2;
#pragma unroll
    for (int i = 0; i < 4; i++) {
#pragma unroll
        for (int j = 0; j < 4; j++) {
            int n = nbase + j * 8;
#pragma unroll
            for (int h = 0; h < 2; h++) {
                int m = rbase + i * 16 + h * 8;
                float v0 = acc[i][j][2 * h];
                float v1 = acc[i][j][2 * h + 1];
                if (MODE == 0) {
                    __half* Cq = (__half*)Chv;
                    size_t crow = (size_t)m * ldc;
                    float q0 = v0 + aux[n], q1 = v1 + aux[n + 1];
                    __half2 s2; s2.x = __float2half(q0 * q0); s2.y = __float2half(q1 * q1);
                    *(__half2*)(Cq + crow + n) = s2;
                    __half2 qq; qq.x = __float2half(q0); qq.y = __float2half(q1);
                    *(__half2*)(Cq + crow + 512 + n) = qq;
                } else if (MODE == 1) {
                    const float scale = -0.5f / (float)DD;
                    size_t crow = (size_t)m * ldc;
                    float2 o;
                    o.x = scale * (v0 + aux[n]);
                    o.y = scale * (v1 + aux[n + 1]);
                    *(float2*)(Cf + crow + n) = o;
                } else if (MODE == 2) {
                    __half* Ch = (__half*)Chv;
                    size_t crow = bz * sC + (size_t)m * ldc;
                    float q0 = v0 + aux[n], q1 = v1 + aux[n + 1];
                    __half2 hh; hh.x = __float2half(q0); hh.y = __float2half(q1);
                    *(__half2*)(Ch + crow + n) = hh;
                } else {
                    size_t crow = bz * sC + (size_t)m * ldc;
                    float2 o; o.x = v0; o.y = v1;
                    *(float2*)(Cf + crow + n) = o;
                }
            }
        }
    }
}

// ---------------------------------------------------------------------------
// softmax over R: reads fp32 g_z (scaled logits), writes fp16 Fss
// ---------------------------------------------------------------------------
__global__ void softmax_kernel() {
    int row = blockIdx.x;
    int t = threadIdx.x;  // 256
    const float* zrow = g_z + (size_t)row * RR;
    float v0 = zrow[t];
    float v1 = zrow[t + 256];
    float m = fmaxf(v0, v1);
#pragma unroll
    for (int o = 16; o > 0; o >>= 1) m = fmaxf(m, __shfl_xor_sync(0xffffffffu, m, o));
    __shared__ float sm[8];
    __shared__ float ss[8];
    int wid = t >> 5, lid = t & 31;
    if (lid == 0) sm[wid] = m;
    __syncthreads();
    float mm = sm[0];
#pragma unroll
    for (int i = 1; i < 8; i++) mm = fmaxf(mm, sm[i]);
    float e0 = __expf(v0 - mm), e1 = __expf(v1 - mm);
    float s = e0 + e1;
#pragma unroll
    for (int o = 16; o > 0; o >>= 1) s += __shfl_xor_sync(0xffffffffu, s, o);
    if (lid == 0) ss[wid] = s;
    __syncthreads();
    float tot = 0.f;
#pragma unroll
    for (int i = 0; i < 8; i++) tot += ss[i];
    float inv = 1.0f / tot;
    size_t i0 = (size_t)row * RR + t;
    g_fss16[i0] = __float2half(e0 * inv);
    g_fss16[i0 + 256] = __float2half(e1 * inv);
}

// ---------------------------------------------------------------------------
extern "C" void kernel_launch(void* const* d_in, const int* in_sizes, int n_in,
                              void* d_out, int out_size) {
    const float* query   = (const float*)d_in[0];   // (B,L,D)
    const float* Wq      = (const float*)d_in[1];   // (D,D)
    const float* bq      = (const float*)d_in[2];   // (D,)
    const float* Wc      = (const float*)d_in[3];   // (R,L)
    const float* bc      = (const float*)d_in[4];   // (R,)
    const float* centers = (const float*)d_in[5];   // (R,D)
    const float* widths  = (const float*)d_in[6];   // (R,D)
    float* out = (float*)d_out;                     // (B,L,D)

    const int SMEM_K1 = 2 * 3 * TILE_B;   // 110592
    const int SMEM_K2 = 2 * 2 * TILE_B;   // 73728
    cudaFuncSetAttribute(gemm_s<0, 1>, cudaFuncAttributeMaxDynamicSharedMemorySize, SMEM_K1);
    cudaFuncSetAttribute(gemm_s<1, 2>, cudaFuncAttributeMaxDynamicSharedMemorySize, SMEM_K2);
    cudaFuncSetAttribute(gemm_s<2, 2>, cudaFuncAttributeMaxDynamicSharedMemorySize, SMEM_K2);
    cudaFuncSetAttribute(gemm_s<3, 2>, cudaFuncAttributeMaxDynamicSharedMemorySize, SMEM_K2);

    __half *q16, *wq16h, *wq16l, *qcat16, *bcat16;
    __half *qT16, *wc16, *fss16, *cq16;
    float *zp, *ccp;
    cudaGetSymbolAddress((void**)&q16, g_q16);
    cudaGetSymbolAddress((void**)&wq16h, g_wq16h);
    cudaGetSymbolAddress((void**)&wq16l, g_wq16l);
    cudaGetSymbolAddress((void**)&qcat16, g_qcat16);
    cudaGetSymbolAddress((void**)&bcat16, g_bcat16);
    cudaGetSymbolAddress((void**)&qT16, g_qT16);
    cudaGetSymbolAddress((void**)&wc16, g_wc16);
    cudaGetSymbolAddress((void**)&fss16, g_fss16);
    cudaGetSymbolAddress((void**)&cq16, g_cq16);
    cudaGetSymbolAddress((void**)&zp, g_z);
    cudaGetSymbolAddress((void**)&ccp, g_cc);

    // prep: weight conversions + query dual-format + rule params
    {
        int n4 = (DD * DD) / 4;
        split16_kernel<<<(n4 + 255) / 256, 256>>>(Wq, wq16h, wq16l, n4);
        n4 = (RR * LL) / 4;
        tofp16_kernel<<<(n4 + 255) / 256, 256>>>(Wc, wc16, n4);
    }
    prep_kernel<<<RR, 128>>>(centers, widths);
    {
        dim3 g(LL / 32, DD / 32, BB);
        dim3 b(32, 8);
        query_prep_kernel<<<g, b>>>(query);
    }

    // G1 (fp16 2-pass): q = query @ Wq^T + bq -> qcat16 = [q^2 | q]
    {
        dim3 g(DD / 128, M1 / 128, 1);
        gemm_s<0, 1><<<g, 256, SMEM_K1>>>(
            (const uint16_t*)q16, DD, 0,
            (const uint16_t*)wq16h, (const uint16_t*)wq16l, DD, 0,
            nullptr, qcat16, 1024, 0, bq, DD);
    }
    // G2 (fp16 1-pass): z = scale * (qcat16 @ bcat16^T + cc)   (K=1024)
    {
        dim3 g(RR / 128, M1 / 128, 1);
        gemm_s<1, 2><<<g, 256, SMEM_K2>>>(
            (const uint16_t*)qcat16, 1024, 0,
            (const uint16_t*)bcat16, nullptr, 1024, 0,
            zp, nullptr, RR, 0, ccp, 1024);
    }
    softmax_kernel<<<M1, 256>>>();
    // G4 (fp16 1-pass): conqT[b] = qT[b] @ Wc^T + bc  (M=D, N=R, K=L)
    {
        dim3 g(RR / 128, DD / 128, BB);
        gemm_s<2, 2><<<g, 256, SMEM_K2>>>(
            (const uint16_t*)qT16, LL, (size_t)DD * LL,
            (const uint16_t*)wc16, nullptr, LL, 0,
            nullptr, cq16, RR, (size_t)DD * RR, bc, LL);
    }
    // G5 (fp16 1-pass): out[b] = Fss[b] @ conqT[b]^T  (M=L, N=D, K=R)
    {
        dim3 g(DD / 128, LL / 128, BB);
        gemm_s<3, 2><<<g, 256, SMEM_K2>>>(
            (const uint16_t*)fss16, RR, (size_t)LL * RR,
            (const uint16_t*)cq16, nullptr, RR, (size_t)DD * RR,
            out, nullptr, DD, (size_t)LL * DD, nullptr, RR);
    }
}

// round 15
// speedup vs baseline: 2.3982x; 1.1068x over previous
#include <cuda_runtime.h>
#include <cuda_bf16.h>
#include <cuda_fp16.h>
#include <cstdint>

// Problem constants
#define BB 8
#define LL 2048
#define DD 512
#define RR 512
#define M1 (BB * LL)   // 16384 flattened (B,L)

__device__ __forceinline__ uint32_t smem_to_u32(const void* smem_ptr) {
    uint32_t addr;
    asm("{ .reg .u64 tmp; cvta.to.shared.u64 tmp, %1; cvt.u32.u64 %0, tmp; }"
        : "=r"(addr) : "l"(smem_ptr));
    return addr;
}

#define CPASYNC16(dst, src) \
    asm volatile("cp.async.cg.shared.global [%0], [%1], 16;" :: "r"(dst), "l"(src))
#define CPASYNC_COMMIT() asm volatile("cp.async.commit_group;" ::: "memory")

#define LDSM4(r0, r1, r2, r3, addr) \
    asm volatile("ldmatrix.sync.aligned.m8n8.x4.shared.b16 {%0,%1,%2,%3}, [%4];" \
                 : "=r"(r0), "=r"(r1), "=r"(r2), "=r"(r3) : "r"(addr))

__device__ __forceinline__ void mma_hf(float* c, const uint32_t* a, const uint32_t* b) {
    asm volatile("mma.sync.aligned.m16n8k16.row.col.f32.f16.f16.f32 "
                 "{%0,%1,%2,%3}, {%4,%5,%6,%7}, {%8,%9}, {%0,%1,%2,%3};"
                 : "+f"(c[0]), "+f"(c[1]), "+f"(c[2]), "+f"(c[3])
                 : "r"(a[0]), "r"(a[1]), "r"(a[2]), "r"(a[3]),
                   "r"(b[0]), "r"(b[1]));
}

// ---------------- scratch (device globals; no allocation allowed) ----------
__device__ __half g_q16[(size_t)M1 * DD];        // query row-major fp16
__device__ __half g_wq16[DD * DD];               // Wq fp16 single
__device__ __half g_qcat16[(size_t)M1 * 1024];   // [q^2 | q], fp16 single
__device__ __half g_bcat16[RR * 1024];           // [invw2 | -2c*invw2] fp16
__device__ float  g_z[(size_t)M1 * RR];
__device__ float  g_cc[RR];
__device__ __half g_qT16[(size_t)BB * DD * LL];  // transposed query
__device__ __half g_wc16[RR * LL];
__device__ __half g_fss16[(size_t)M1 * RR];
__device__ __half g_cq16[(size_t)BB * DD * RR];  // conqT

// ---------------------------------------------------------------------------
// tofp16: fp32 -> fp16 single (for Wq, Wc)
// ---------------------------------------------------------------------------
__global__ void tofp16_kernel(const float* __restrict__ src, __half* __restrict__ dst,
                              int n4) {
    int i = blockIdx.x * blockDim.x + threadIdx.x;
    if (i >= n4) return;
    float4 v = ((const float4*)src)[i];
    __half2 a0; a0.x = __float2half(v.x); a0.y = __float2half(v.y);
    __half2 a1; a1.x = __float2half(v.z); a1.y = __float2half(v.w);
    ((__half2*)dst)[i * 2 + 0] = a0;
    ((__half2*)dst)[i * 2 + 1] = a1;
}

// ---------------------------------------------------------------------------
// query prep: single read -> row-major fp16 (G1) + transposed fp16 (G4)
// ---------------------------------------------------------------------------
__global__ void query_prep_kernel(const float* __restrict__ query) {
    __shared__ float tile[32][33];
    int b = blockIdx.z;
    int l0 = blockIdx.x * 32, d0 = blockIdx.y * 32;
    int tx = threadIdx.x, ty = threadIdx.y;
    const float* src = query + (size_t)b * LL * DD;
#pragma unroll
    for (int i = 0; i < 4; i++) {
        int l = l0 + ty + 8 * i;
        float v = src[(size_t)l * DD + d0 + tx];
        tile[ty + 8 * i][tx] = v;
        size_t idx = (size_t)(b * LL + l) * DD + d0 + tx;
        g_q16[idx] = __float2half(v);
    }
    __syncthreads();
    size_t base = (size_t)b * DD * LL;
#pragma unroll
    for (int i = 0; i < 4; i++) {
        float v = tile[tx][ty + 8 * i];
        size_t idx = base + (size_t)(d0 + ty + 8 * i) * LL + l0 + tx;
        g_qT16[idx] = __float2half(v);
    }
}

// ---------------------------------------------------------------------------
// prep: bcat = [invw2 | -2c*invw2] fp16 single, cc[r] = sum c^2*invw2
// ---------------------------------------------------------------------------
__global__ void prep_kernel(const float* __restrict__ centers,
                            const float* __restrict__ widths) {
    int r = blockIdx.x;
    int t = threadIdx.x;  // 128
    float acc = 0.f;
    for (int d = t; d < DD; d += 128) {
        float w = widths[r * DD + d];
        float c = centers[r * DD + d];
        float iw = 1.0f / (w * w);
        float b2 = -2.0f * c * iw;
        g_bcat16[r * 1024 + d] = __float2half(iw);
        g_bcat16[r * 1024 + 512 + d] = __float2half(b2);
        acc += c * c * iw;
    }
    __shared__ float sred[128];
    sred[t] = acc;
    __syncthreads();
    for (int s = 64; s > 0; s >>= 1) {
        if (t < s) sred[t] += sred[t + s];
        __syncthreads();
    }
    if (t == 0) g_cc[r] = sred[0];
}

// ---------------------------------------------------------------------------
// fp16 1-pass NT GEMM via mma.sync m16n8k16 (A and B single fp16).
// 128x128 CTA tile, 8 warps of 64x32. K-chunk 64, 2-stage cp.async pipeline.
// SMEM tile: 128 rows x 128B data, 144B pitch (conflict-free ldmatrix+store).
// MODE 0: qcat ((v+aux)^2 | (v+aux)) -> single fp16 (Chv; ldc=1024)
// MODE 1: fp32 scale*(v+aux[n]) -> Cf
// MODE 2: fp16 single v+aux[n]  -> Chv (as __half*)
// MODE 3: fp32 raw              -> Cf
// ---------------------------------------------------------------------------
#define TPITCH 144
#define TILE_B (128 * TPITCH)        // 18432
#define STB (2 * TILE_B)             // A + B per stage
#define GEMM_SMEM (2 * STB)          // 73728

template <int MODE>
__global__ __launch_bounds__(256, 1) void gemm_s(
    const uint16_t* __restrict__ Ah, int lda, size_t sA,
    const uint16_t* __restrict__ Bh, int ldb, size_t sB,
    float* __restrict__ Cf, void* __restrict__ Chv,
    int ldc, size_t sC, const float* __restrict__ aux, int K) {
    extern __shared__ char smem[];
    uint32_t sb = smem_to_u32(smem);
    int t = threadIdx.x;
    int lane = t & 31, wid = t >> 5;
    int wm = wid & 1, wn = wid >> 1;
    int bn = blockIdx.x * 128, bm = blockIdx.y * 128;
    size_t bz = blockIdx.z;
    Ah += bz * sA;
    Bh += bz * sB;

    // cp.async plan: each thread covers rows r0+32i, one 16B column, per tile.
    int r0 = t >> 3;
    int cc = t & 7;
    const uint16_t* gA = Ah + (size_t)(bm + r0) * lda + cc * 8;
    const uint16_t* gB = Bh + (size_t)(bn + r0) * ldb + cc * 8;
    uint32_t soff = (uint32_t)(r0 * TPITCH + cc * 16);

    float acc[4][4][4] = {};
    const int nk = K >> 6;

    // prologue: chunk 0 -> stage 0
    {
#pragma unroll
        for (int i = 0; i < 4; i++) {
            uint32_t o = soff + (uint32_t)(i * 32 * TPITCH);
            CPASYNC16(sb + o,          gA + (size_t)(32 * i) * lda);
            CPASYNC16(sb + TILE_B + o, gB + (size_t)(32 * i) * ldb);
        }
        CPASYNC_COMMIT();
    }

    int lm = lane & 15, lq = lane >> 4;
    uint32_t a_base = (uint32_t)((wm * 64 + lm) * TPITCH);
    uint32_t b_base = (uint32_t)((wn * 32 + lm) * TPITCH);

    for (int kt = 0; kt < nk; kt++) {
        int buf = kt & 1;
        if (kt + 1 < nk) {
            uint32_t db = sb + (buf ^ 1) * STB;
            int koff = (kt + 1) * 64;
#pragma unroll
            for (int i = 0; i < 4; i++) {
                uint32_t o = soff + (uint32_t)(i * 32 * TPITCH);
                CPASYNC16(db + o,          gA + (size_t)(32 * i) * lda + koff);
                CPASYNC16(db + TILE_B + o, gB + (size_t)(32 * i) * ldb + koff);
            }
            CPASYNC_COMMIT();
            asm volatile("cp.async.wait_group 1;" ::: "memory");
        } else {
            asm volatile("cp.async.wait_group 0;" ::: "memory");
        }
        __syncthreads();
        uint32_t base = sb + buf * STB;
#pragma unroll
        for (int ks = 0; ks < 4; ks++) {
            uint32_t off16 = (uint32_t)((2 * ks + lq) * 16);
            uint32_t a[4][4], bb[4][2];
#pragma unroll
            for (int i = 0; i < 4; i++)
                LDSM4(a[i][0], a[i][1], a[i][2], a[i][3],
                      base + a_base + i * (16 * TPITCH) + off16);
#pragma unroll
            for (int jj = 0; jj < 2; jj++) {
                uint32_t q0, q1, q2, q3;
                LDSM4(q0, q1, q2, q3,
                      base + TILE_B + b_base + jj * (16 * TPITCH) + off16);
                bb[2 * jj][0] = q0; bb[2 * jj][1] = q2;
                bb[2 * jj + 1][0] = q1; bb[2 * jj + 1][1] = q3;
            }
#pragma unroll
            for (int i = 0; i < 4; i++)
#pragma unroll
                for (int j = 0; j < 4; j++) mma_hf(acc[i][j], a[i], bb[j]);
        }
        __syncthreads();
    }

    // epilogue (register-direct)
    int rbase = bm + wm * 64 + (lane >> 2);
    int nbase = bn + wn * 32 + (lane & 3) * 2;
#pragma unroll
    for (int i = 0; i < 4; i++) {
#pragma unroll
        for (int j = 0; j < 4; j++) {
            int n = nbase + j * 8;
#pragma unroll
            for (int h = 0; h < 2; h++) {
                int m = rbase + i * 16 + h * 8;
                float v0 = acc[i][j][2 * h];
                float v1 = acc[i][j][2 * h + 1];
                if (MODE == 0) {
                    __half* Cq = (__half*)Chv;
                    size_t crow = (size_t)m * ldc;
                    float q0 = v0 + aux[n], q1 = v1 + aux[n + 1];
                    __half2 s2; s2.x = __float2half(q0 * q0); s2.y = __float2half(q1 * q1);
                    *(__half2*)(Cq + crow + n) = s2;
                    __half2 qq; qq.x = __float2half(q0); qq.y = __float2half(q1);
                    *(__half2*)(Cq + crow + 512 + n) = qq;
                } else if (MODE == 1) {
                    const float scale = -0.5f / (float)DD;
                    size_t crow = (size_t)m * ldc;
                    float2 o;
                    o.x = scale * (v0 + aux[n]);
                    o.y = scale * (v1 + aux[n + 1]);
                    *(float2*)(Cf + crow + n) = o;
                } else if (MODE == 2) {
                    __half* Ch = (__half*)Chv;
                    size_t crow = bz * sC + (size_t)m * ldc;
                    float q0 = v0 + aux[n], q1 = v1 + aux[n + 1];
                    __half2 hh; hh.x = __float2half(q0); hh.y = __float2half(q1);
                    *(__half2*)(Ch + crow + n) = hh;
                } else {
                    size_t crow = bz * sC + (size_t)m * ldc;
                    float2 o; o.x = v0; o.y = v1;
                    *(float2*)(Cf + crow + n) = o;
                }
            }
        }
    }
}

// ---------------------------------------------------------------------------
// softmax over R: reads fp32 g_z (scaled logits), writes fp16 Fss
// ---------------------------------------------------------------------------
__global__ void softmax_kernel() {
    int row = blockIdx.x;
    int t = threadIdx.x;  // 256
    const float* zrow = g_z + (size_t)row * RR;
    float v0 = zrow[t];
    float v1 = zrow[t + 256];
    float m = fmaxf(v0, v1);
#pragma unroll
    for (int o = 16; o > 0; o >>= 1) m = fmaxf(m, __shfl_xor_sync(0xffffffffu, m, o));
    __shared__ float sm[8];
    __shared__ float ss[8];
    int wid = t >> 5, lid = t & 31;
    if (lid == 0) sm[wid] = m;
    __syncthreads();
    float mm = sm[0];
#pragma unroll
    for (int i = 1; i < 8; i++) mm = fmaxf(mm, sm[i]);
    float e0 = __expf(v0 - mm), e1 = __expf(v1 - mm);
    float s = e0 + e1;
#pragma unroll
    for (int o = 16; o > 0; o >>= 1) s += __shfl_xor_sync(0xffffffffu, s, o);
    if (lid == 0) ss[wid] = s;
    __syncthreads();
    float tot = 0.f;
#pragma unroll
    for (int i = 0; i < 8; i++) tot += ss[i];
    float inv = 1.0f / tot;
    size_t i0 = (size_t)row * RR + t;
    g_fss16[i0] = __float2half(e0 * inv);
    g_fss16[i0 + 256] = __float2half(e1 * inv);
}

// ---------------------------------------------------------------------------
extern "C" void kernel_launch(void* const* d_in, const int* in_sizes, int n_in,
                              void* d_out, int out_size) {
    const float* query   = (const float*)d_in[0];   // (B,L,D)
    const float* Wq      = (const float*)d_in[1];   // (D,D)
    const float* bq      = (const float*)d_in[2];   // (D,)
    const float* Wc      = (const float*)d_in[3];   // (R,L)
    const float* bc      = (const float*)d_in[4];   // (R,)
    const float* centers = (const float*)d_in[5];   // (R,D)
    const float* widths  = (const float*)d_in[6];   // (R,D)
    float* out = (float*)d_out;                     // (B,L,D)

    cudaFuncSetAttribute(gemm_s<0>, cudaFuncAttributeMaxDynamicSharedMemorySize, GEMM_SMEM);
    cudaFuncSetAttribute(gemm_s<1>, cudaFuncAttributeMaxDynamicSharedMemorySize, GEMM_SMEM);
    cudaFuncSetAttribute(gemm_s<2>, cudaFuncAttributeMaxDynamicSharedMemorySize, GEMM_SMEM);
    cudaFuncSetAttribute(gemm_s<3>, cudaFuncAttributeMaxDynamicSharedMemorySize, GEMM_SMEM);

    __half *q16, *wq16, *qcat16, *bcat16;
    __half *qT16, *wc16, *fss16, *cq16;
    float *zp, *ccp;
    cudaGetSymbolAddress((void**)&q16, g_q16);
    cudaGetSymbolAddress((void**)&wq16, g_wq16);
    cudaGetSymbolAddress((void**)&qcat16, g_qcat16);
    cudaGetSymbolAddress((void**)&bcat16, g_bcat16);
    cudaGetSymbolAddress((void**)&qT16, g_qT16);
    cudaGetSymbolAddress((void**)&wc16, g_wc16);
    cudaGetSymbolAddress((void**)&fss16, g_fss16);
    cudaGetSymbolAddress((void**)&cq16, g_cq16);
    cudaGetSymbolAddress((void**)&zp, g_z);
    cudaGetSymbolAddress((void**)&ccp, g_cc);

    // prep: weight conversions + query dual-format + rule params
    {
        int n4 = (DD * DD) / 4;
        tofp16_kernel<<<(n4 + 255) / 256, 256>>>(Wq, wq16, n4);
        n4 = (RR * LL) / 4;
        tofp16_kernel<<<(n4 + 255) / 256, 256>>>(Wc, wc16, n4);
    }
    prep_kernel<<<RR, 128>>>(centers, widths);
    {
        dim3 g(LL / 32, DD / 32, BB);
        dim3 b(32, 8);
        query_prep_kernel<<<g, b>>>(query);
    }

    // G1 (fp16 1-pass): q = query @ Wq^T + bq -> qcat16 = [q^2 | q]
    {
        dim3 g(DD / 128, M1 / 128, 1);
        gemm_s<0><<<g, 256, GEMM_SMEM>>>(
            (const uint16_t*)q16, DD, 0,
            (const uint16_t*)wq16, DD, 0,
            nullptr, qcat16, 1024, 0, bq, DD);
    }
    // G2 (fp16 1-pass): z = scale * (qcat16 @ bcat16^T + cc)   (K=1024)
    {
        dim3 g(RR / 128, M1 / 128, 1);
        gemm_s<1><<<g, 256, GEMM_SMEM>>>(
            (const uint16_t*)qcat16, 1024, 0,
            (const uint16_t*)bcat16, 1024, 0,
            zp, nullptr, RR, 0, ccp, 1024);
    }
    softmax_kernel<<<M1, 256>>>();
    // G4 (fp16 1-pass): conqT[b] = qT[b] @ Wc^T + bc  (M=D, N=R, K=L)
    {
        dim3 g(RR / 128, DD / 128, BB);
        gemm_s<2><<<g, 256, GEMM_SMEM>>>(
            (const uint16_t*)qT16, LL, (size_t)DD * LL,
            (const uint16_t*)wc16, LL, 0,
            nullptr, cq16, RR, (size_t)DD * RR, bc, LL);
    }
    // G5 (fp16 1-pass): out[b] = Fss[b] @ conqT[b]^T  (M=L, N=D, K=R)
    {
        dim3 g(DD / 128, LL / 128, BB);
        gemm_s<3><<<g, 256, GEMM_SMEM>>>(
            (const uint16_t*)fss16, RR, (size_t)LL * RR,
            (const uint16_t*)cq16, RR, (size_t)DD * RR,
            out, nullptr, DD, (size_t)LL * DD, nullptr, RR);
    }
}

// round 16
// speedup vs baseline: 2.4179x; 1.0082x over previous
#include <cuda_runtime.h>
#include <cuda_bf16.h>
#include <cuda_fp16.h>
#include <cstdint>

// Problem constants
#define BB 8
#define LL 2048
#define DD 512
#define RR 512
#define M1 (BB * LL)   // 16384 flattened (B,L)

__device__ __forceinline__ uint32_t smem_to_u32(const void* smem_ptr) {
    uint32_t addr;
    asm("{ .reg .u64 tmp; cvta.to.shared.u64 tmp, %1; cvt.u32.u64 %0, tmp; }"
        : "=r"(addr) : "l"(smem_ptr));
    return addr;
}

#define CPASYNC16(dst, src) \
    asm volatile("cp.async.cg.shared.global [%0], [%1], 16;" :: "r"(dst), "l"(src))
#define CPASYNC_COMMIT() asm volatile("cp.async.commit_group;" ::: "memory")

#define LDSM4(r0, r1, r2, r3, addr) \
    asm volatile("ldmatrix.sync.aligned.m8n8.x4.shared.b16 {%0,%1,%2,%3}, [%4];" \
                 : "=r"(r0), "=r"(r1), "=r"(r2), "=r"(r3) : "r"(addr))

__device__ __forceinline__ void mma_hf(float* c, const uint32_t* a, const uint32_t* b) {
    asm volatile("mma.sync.aligned.m16n8k16.row.col.f32.f16.f16.f32 "
                 "{%0,%1,%2,%3}, {%4,%5,%6,%7}, {%8,%9}, {%0,%1,%2,%3};"
                 : "+f"(c[0]), "+f"(c[1]), "+f"(c[2]), "+f"(c[3])
                 : "r"(a[0]), "r"(a[1]), "r"(a[2]), "r"(a[3]),
                   "r"(b[0]), "r"(b[1]));
}

// ---------------- scratch (device globals; no allocation allowed) ----------
__device__ __half g_q16[(size_t)M1 * DD];        // query row-major fp16
__device__ __half g_wq16[DD * DD];               // Wq fp16 single
__device__ __half g_qcat16[(size_t)M1 * 1024];   // [q^2 | q], fp16 single
__device__ __half g_bcat16[RR * 1024];           // [invw2 | -2c*invw2] fp16
__device__ float  g_z[(size_t)M1 * RR];
__device__ float  g_cc[RR];
__device__ __half g_qT16[(size_t)BB * DD * LL];  // transposed query
__device__ __half g_wc16[RR * LL];
__device__ __half g_fss16[(size_t)M1 * RR];
__device__ __half g_cq16[(size_t)BB * DD * RR];  // conqT

// ---------------------------------------------------------------------------
// tofp16: fp32 -> fp16 single (for Wq, Wc)
// ---------------------------------------------------------------------------
__global__ void tofp16_kernel(const float* __restrict__ src, __half* __restrict__ dst,
                              int n4) {
    int i = blockIdx.x * blockDim.x + threadIdx.x;
    if (i >= n4) return;
    float4 v = ((const float4*)src)[i];
    __half2 a0; a0.x = __float2half(v.x); a0.y = __float2half(v.y);
    __half2 a1; a1.x = __float2half(v.z); a1.y = __float2half(v.w);
    ((__half2*)dst)[i * 2 + 0] = a0;
    ((__half2*)dst)[i * 2 + 1] = a1;
}

// ---------------------------------------------------------------------------
// query prep: single read -> row-major fp16 (G1) + transposed fp16 (G4)
// ---------------------------------------------------------------------------
__global__ void query_prep_kernel(const float* __restrict__ query) {
    __shared__ float tile[32][33];
    int b = blockIdx.z;
    int l0 = blockIdx.x * 32, d0 = blockIdx.y * 32;
    int tx = threadIdx.x, ty = threadIdx.y;
    const float* src = query + (size_t)b * LL * DD;
#pragma unroll
    for (int i = 0; i < 4; i++) {
        int l = l0 + ty + 8 * i;
        float v = src[(size_t)l * DD + d0 + tx];
        tile[ty + 8 * i][tx] = v;
        size_t idx = (size_t)(b * LL + l) * DD + d0 + tx;
        g_q16[idx] = __float2half(v);
    }
    __syncthreads();
    size_t base = (size_t)b * DD * LL;
#pragma unroll
    for (int i = 0; i < 4; i++) {
        float v = tile[tx][ty + 8 * i];
        size_t idx = base + (size_t)(d0 + ty + 8 * i) * LL + l0 + tx;
        g_qT16[idx] = __float2half(v);
    }
}

// ---------------------------------------------------------------------------
// prep: bcat = [invw2 | -2c*invw2] fp16 single, cc[r] = sum c^2*invw2
// ---------------------------------------------------------------------------
__global__ void prep_kernel(const float* __restrict__ centers,
                            const float* __restrict__ widths) {
    int r = blockIdx.x;
    int t = threadIdx.x;  // 128
    float acc = 0.f;
    for (int d = t; d < DD; d += 128) {
        float w = widths[r * DD + d];
        float c = centers[r * DD + d];
        float iw = 1.0f / (w * w);
        float b2 = -2.0f * c * iw;
        g_bcat16[r * 1024 + d] = __float2half(iw);
        g_bcat16[r * 1024 + 512 + d] = __float2half(b2);
        acc += c * c * iw;
    }
    __shared__ float sred[128];
    sred[t] = acc;
    __syncthreads();
    for (int s = 64; s > 0; s >>= 1) {
        if (t < s) sred[t] += sred[t + s];
        __syncthreads();
    }
    if (t == 0) g_cc[r] = sred[0];
}

// ---------------------------------------------------------------------------
// fp16 1-pass NT GEMM via mma.sync m16n8k16 (A and B single fp16).
// 128x128 CTA tile, 8 warps of 64x32. K-chunk 64, 2-stage cp.async pipeline.
// 2 CTAs/SM (launch_bounds 256,2) to fill sync bubbles + wave tails.
// SMEM tile: 128 rows x 128B data, 144B pitch (conflict-free ldmatrix+store).
// MODE 0: qcat ((v+aux)^2 | (v+aux)) -> single fp16 (Chv; ldc=1024)
// MODE 1: fp32 scale*(v+aux[n]) -> Cf
// MODE 2: fp16 single v+aux[n]  -> Chv (as __half*)
// MODE 3: fp32 raw              -> Cf
// ---------------------------------------------------------------------------
#define TPITCH 144
#define TILE_B (128 * TPITCH)        // 18432
#define STB (2 * TILE_B)             // A + B per stage
#define GEMM_SMEM (2 * STB)          // 73728

template <int MODE>
__global__ __launch_bounds__(256, 2) void gemm_s(
    const uint16_t* __restrict__ Ah, int lda, size_t sA,
    const uint16_t* __restrict__ Bh, int ldb, size_t sB,
    float* __restrict__ Cf, void* __restrict__ Chv,
    int ldc, size_t sC, const float* __restrict__ aux, int K) {
    extern __shared__ char smem[];
    uint32_t sb = smem_to_u32(smem);
    int t = threadIdx.x;
    int lane = t & 31, wid = t >> 5;
    int wm = wid & 1, wn = wid >> 1;
    int bn = blockIdx.x * 128, bm = blockIdx.y * 128;
    size_t bz = blockIdx.z;
    Ah += bz * sA;
    Bh += bz * sB;

    // cp.async plan: each thread covers rows r0+32i, one 16B column, per tile.
    int r0 = t >> 3;
    int cc = t & 7;
    const uint16_t* gA = Ah + (size_t)(bm + r0) * lda + cc * 8;
    const uint16_t* gB = Bh + (size_t)(bn + r0) * ldb + cc * 8;
    uint32_t soff = (uint32_t)(r0 * TPITCH + cc * 16);

    float acc[4][4][4] = {};
    const int nk = K >> 6;

    // prologue: chunk 0 -> stage 0
    {
#pragma unroll
        for (int i = 0; i < 4; i++) {
            uint32_t o = soff + (uint32_t)(i * 32 * TPITCH);
            CPASYNC16(sb + o,          gA + (size_t)(32 * i) * lda);
            CPASYNC16(sb + TILE_B + o, gB + (size_t)(32 * i) * ldb);
        }
        CPASYNC_COMMIT();
    }

    int lm = lane & 15, lq = lane >> 4;
    uint32_t a_base = (uint32_t)((wm * 64 + lm) * TPITCH);
    uint32_t b_base = (uint32_t)((wn * 32 + lm) * TPITCH);

    for (int kt = 0; kt < nk; kt++) {
        int buf = kt & 1;
        if (kt + 1 < nk) {
            uint32_t db = sb + (buf ^ 1) * STB;
            int koff = (kt + 1) * 64;
#pragma unroll
            for (int i = 0; i < 4; i++) {
                uint32_t o = soff + (uint32_t)(i * 32 * TPITCH);
                CPASYNC16(db + o,          gA + (size_t)(32 * i) * lda + koff);
                CPASYNC16(db + TILE_B + o, gB + (size_t)(32 * i) * ldb + koff);
            }
            CPASYNC_COMMIT();
            asm volatile("cp.async.wait_group 1;" ::: "memory");
        } else {
            asm volatile("cp.async.wait_group 0;" ::: "memory");
        }
        __syncthreads();
        uint32_t base = sb + buf * STB;
#pragma unroll
        for (int ks = 0; ks < 4; ks++) {
            uint32_t off16 = (uint32_t)((2 * ks + lq) * 16);
            uint32_t a[4][4], bb[4][2];
#pragma unroll
            for (int i = 0; i < 4; i++)
                LDSM4(a[i][0], a[i][1], a[i][2], a[i][3],
                      base + a_base + i * (16 * TPITCH) + off16);
#pragma unroll
            for (int jj = 0; jj < 2; jj++) {
                uint32_t q0, q1, q2, q3;
                LDSM4(q0, q1, q2, q3,
                      base + TILE_B + b_base + jj * (16 * TPITCH) + off16);
                bb[2 * jj][0] = q0; bb[2 * jj][1] = q2;
                bb[2 * jj + 1][0] = q1; bb[2 * jj + 1][1] = q3;
            }
#pragma unroll
            for (int i = 0; i < 4; i++)
#pragma unroll
                for (int j = 0; j < 4; j++) mma_hf(acc[i][j], a[i], bb[j]);
        }
        __syncthreads();
    }

    // epilogue (register-direct)
    int rbase = bm + wm * 64 + (lane >> 2);
    int nbase = bn + wn * 32 + (lane & 3) * 2;
#pragma unroll
    for (int i = 0; i < 4; i++) {
#pragma unroll
        for (int j = 0; j < 4; j++) {
            int n = nbase + j * 8;
#pragma unroll
            for (int h = 0; h < 2; h++) {
                int m = rbase + i * 16 + h * 8;
                float v0 = acc[i][j][2 * h];
                float v1 = acc[i][j][2 * h + 1];
                if (MODE == 0) {
                    __half* Cq = (__half*)Chv;
                    size_t crow = (size_t)m * ldc;
                    float q0 = v0 + aux[n], q1 = v1 + aux[n + 1];
                    __half2 s2; s2.x = __float2half(q0 * q0); s2.y = __float2half(q1 * q1);
                    *(__half2*)(Cq + crow + n) = s2;
                    __half2 qq; qq.x = __float2half(q0); qq.y = __float2half(q1);
                    *(__half2*)(Cq + crow + 512 + n) = qq;
                } else if (MODE == 1) {
                    const float scale = -0.5f / (float)DD;
                    size_t crow = (size_t)m * ldc;
                    float2 o;
                    o.x = scale * (v0 + aux[n]);
                    o.y = scale * (v1 + aux[n + 1]);
                    *(float2*)(Cf + crow + n) = o;
                } else if (MODE == 2) {
                    __half* Ch = (__half*)Chv;
                    size_t crow = bz * sC + (size_t)m * ldc;
                    float q0 = v0 + aux[n], q1 = v1 + aux[n + 1];
                    __half2 hh; hh.x = __float2half(q0); hh.y = __float2half(q1);
                    *(__half2*)(Ch + crow + n) = hh;
                } else {
                    size_t crow = bz * sC + (size_t)m * ldc;
                    float2 o; o.x = v0; o.y = v1;
                    *(float2*)(Cf + crow + n) = o;
                }
            }
        }
    }
}

// ---------------------------------------------------------------------------
// softmax over R: reads fp32 g_z (scaled logits), writes fp16 Fss
// ---------------------------------------------------------------------------
__global__ void softmax_kernel() {
    int row = blockIdx.x;
    int t = threadIdx.x;  // 256
    const float* zrow = g_z + (size_t)row * RR;
    float v0 = zrow[t];
    float v1 = zrow[t + 256];
    float m = fmaxf(v0, v1);
#pragma unroll
    for (int o = 16; o > 0; o >>= 1) m = fmaxf(m, __shfl_xor_sync(0xffffffffu, m, o));
    __shared__ float sm[8];
    __shared__ float ss[8];
    int wid = t >> 5, lid = t & 31;
    if (lid == 0) sm[wid] = m;
    __syncthreads();
    float mm = sm[0];
#pragma unroll
    for (int i = 1; i < 8; i++) mm = fmaxf(mm, sm[i]);
    float e0 = __expf(v0 - mm), e1 = __expf(v1 - mm);
    float s = e0 + e1;
#pragma unroll
    for (int o = 16; o > 0; o >>= 1) s += __shfl_xor_sync(0xffffffffu, s, o);
    if (lid == 0) ss[wid] = s;
    __syncthreads();
    float tot = 0.f;
#pragma unroll
    for (int i = 0; i < 8; i++) tot += ss[i];
    float inv = 1.0f / tot;
    size_t i0 = (size_t)row * RR + t;
    g_fss16[i0] = __float2half(e0 * inv);
    g_fss16[i0 + 256] = __float2half(e1 * inv);
}

// ---------------------------------------------------------------------------
extern "C" void kernel_launch(void* const* d_in, const int* in_sizes, int n_in,
                              void* d_out, int out_size) {
    const float* query   = (const float*)d_in[0];   // (B,L,D)
    const float* Wq      = (const float*)d_in[1];   // (D,D)
    const float* bq      = (const float*)d_in[2];   // (D,)
    const float* Wc      = (const float*)d_in[3];   // (R,L)
    const float* bc      = (const float*)d_in[4];   // (R,)
    const float* centers = (const float*)d_in[5];   // (R,D)
    const float* widths  = (const float*)d_in[6];   // (R,D)
    float* out = (float*)d_out;                     // (B,L,D)

    cudaFuncSetAttribute(gemm_s<0>, cudaFuncAttributeMaxDynamicSharedMemorySize, GEMM_SMEM);
    cudaFuncSetAttribute(gemm_s<1>, cudaFuncAttributeMaxDynamicSharedMemorySize, GEMM_SMEM);
    cudaFuncSetAttribute(gemm_s<2>, cudaFuncAttributeMaxDynamicSharedMemorySize, GEMM_SMEM);
    cudaFuncSetAttribute(gemm_s<3>, cudaFuncAttributeMaxDynamicSharedMemorySize, GEMM_SMEM);

    __half *q16, *wq16, *qcat16, *bcat16;
    __half *qT16, *wc16, *fss16, *cq16;
    float *zp, *ccp;
    cudaGetSymbolAddress((void**)&q16, g_q16);
    cudaGetSymbolAddress((void**)&wq16, g_wq16);
    cudaGetSymbolAddress((void**)&qcat16, g_qcat16);
    cudaGetSymbolAddress((void**)&bcat16, g_bcat16);
    cudaGetSymbolAddress((void**)&qT16, g_qT16);
    cudaGetSymbolAddress((void**)&wc16, g_wc16);
    cudaGetSymbolAddress((void**)&fss16, g_fss16);
    cudaGetSymbolAddress((void**)&cq16, g_cq16);
    cudaGetSymbolAddress((void**)&zp, g_z);
    cudaGetSymbolAddress((void**)&ccp, g_cc);

    // prep: weight conversions + query dual-format + rule params
    {
        int n4 = (DD * DD) / 4;
        tofp16_kernel<<<(n4 + 255) / 256, 256>>>(Wq, wq16, n4);
        n4 = (RR * LL) / 4;
        tofp16_kernel<<<(n4 + 255) / 256, 256>>>(Wc, wc16, n4);
    }
    prep_kernel<<<RR, 128>>>(centers, widths);
    {
        dim3 g(LL / 32, DD / 32, BB);
        dim3 b(32, 8);
        query_prep_kernel<<<g, b>>>(query);
    }

    // G1 (fp16 1-pass): q = query @ Wq^T + bq -> qcat16 = [q^2 | q]
    {
        dim3 g(DD / 128, M1 / 128, 1);
        gemm_s<0><<<g, 256, GEMM_SMEM>>>(
            (const uint16_t*)q16, DD, 0,
            (const uint16_t*)wq16, DD, 0,
            nullptr, qcat16, 1024, 0, bq, DD);
    }
    // G2 (fp16 1-pass): z = scale * (qcat16 @ bcat16^T + cc)   (K=1024)
    {
        dim3 g(RR / 128, M1 / 128, 1);
        gemm_s<1><<<g, 256, GEMM_SMEM>>>(
            (const uint16_t*)qcat16, 1024, 0,
            (const uint16_t*)bcat16, 1024, 0,
            zp, nullptr, RR, 0, ccp, 1024);
    }
    softmax_kernel<<<M1, 256>>>();
    // G4 (fp16 1-pass): conqT[b] = qT[b] @ Wc^T + bc  (M=D, N=R, K=L)
    {
        dim3 g(RR / 128, DD / 128, BB);
        gemm_s<2><<<g, 256, GEMM_SMEM>>>(
            (const uint16_t*)qT16, LL, (size_t)DD * LL,
            (const uint16_t*)wc16, LL, 0,
            nullptr, cq16, RR, (size_t)DD * RR, bc, LL);
    }
    // G5 (fp16 1-pass): out[b] = Fss[b] @ conqT[b]^T  (M=L, N=D, K=R)
    {
        dim3 g(DD / 128, LL / 128, BB);
        gemm_s<3><<<g, 256, GEMM_SMEM>>>(
            (const uint16_t*)fss16, RR, (size_t)LL * RR,
            (const uint16_t*)cq16, RR, (size_t)DD * RR,
            out, nullptr, DD, (size_t)LL * DD, nullptr, RR);
    }
}

// round 17
// speedup vs baseline: 2.5288x; 1.0459x over previous
#include <cuda_runtime.h>
#include <cuda_bf16.h>
#include <cuda_fp16.h>
#include <cstdint>

// Problem constants
#define BB 8
#define LL 2048
#define DD 512
#define RR 512
#define M1 (BB * LL)   // 16384 flattened (B,L)

__device__ __forceinline__ uint32_t smem_to_u32(const void* smem_ptr) {
    uint32_t addr;
    asm("{ .reg .u64 tmp; cvta.to.shared.u64 tmp, %1; cvt.u32.u64 %0, tmp; }"
        : "=r"(addr) : "l"(smem_ptr));
    return addr;
}

#define CPASYNC16(dst, src) \
    asm volatile("cp.async.cg.shared.global [%0], [%1], 16;" :: "r"(dst), "l"(src))
#define CPASYNC_COMMIT() asm volatile("cp.async.commit_group;" ::: "memory")

#define LDSM4(r0, r1, r2, r3, addr) \
    asm volatile("ldmatrix.sync.aligned.m8n8.x4.shared.b16 {%0,%1,%2,%3}, [%4];" \
                 : "=r"(r0), "=r"(r1), "=r"(r2), "=r"(r3) : "r"(addr))

__device__ __forceinline__ void mma_hf(float* c, const uint32_t* a, const uint32_t* b) {
    asm volatile("mma.sync.aligned.m16n8k16.row.col.f32.f16.f16.f32 "
                 "{%0,%1,%2,%3}, {%4,%5,%6,%7}, {%8,%9}, {%0,%1,%2,%3};"
                 : "+f"(c[0]), "+f"(c[1]), "+f"(c[2]), "+f"(c[3])
                 : "r"(a[0]), "r"(a[1]), "r"(a[2]), "r"(a[3]),
                   "r"(b[0]), "r"(b[1]));
}

// ---------------- scratch (device globals; no allocation allowed) ----------
__device__ __half g_q16[(size_t)M1 * DD];        // query row-major fp16
__device__ __half g_wq16[DD * DD];               // Wq fp16 single
__device__ __half g_qcat16[(size_t)M1 * 1024];   // [q^2 | q], fp16 single
__device__ __half g_bcat16[RR * 1024];           // [invw2 | -2c*invw2] fp16
__device__ float  g_cc[RR];
__device__ __half g_e16[(size_t)M1 * RR];        // exp(z), unnormalized
__device__ float  g_rinv[M1];                    // 1 / rowsum(e)
__device__ __half g_qT16[(size_t)BB * DD * LL];  // transposed query
__device__ __half g_wc16[RR * LL];
__device__ __half g_cq16[(size_t)BB * DD * RR];  // conqT

// ---------------------------------------------------------------------------
// tofp16: fp32 -> fp16 single (for Wq, Wc)
// ---------------------------------------------------------------------------
__global__ void tofp16_kernel(const float* __restrict__ src, __half* __restrict__ dst,
                              int n4) {
    int i = blockIdx.x * blockDim.x + threadIdx.x;
    if (i >= n4) return;
    float4 v = ((const float4*)src)[i];
    __half2 a0; a0.x = __float2half(v.x); a0.y = __float2half(v.y);
    __half2 a1; a1.x = __float2half(v.z); a1.y = __float2half(v.w);
    ((__half2*)dst)[i * 2 + 0] = a0;
    ((__half2*)dst)[i * 2 + 1] = a1;
}

// ---------------------------------------------------------------------------
// query prep: single read -> row-major fp16 (G1) + transposed fp16 (G4)
// ---------------------------------------------------------------------------
__global__ void query_prep_kernel(const float* __restrict__ query) {
    __shared__ float tile[32][33];
    int b = blockIdx.z;
    int l0 = blockIdx.x * 32, d0 = blockIdx.y * 32;
    int tx = threadIdx.x, ty = threadIdx.y;
    const float* src = query + (size_t)b * LL * DD;
#pragma unroll
    for (int i = 0; i < 4; i++) {
        int l = l0 + ty + 8 * i;
        float v = src[(size_t)l * DD + d0 + tx];
        tile[ty + 8 * i][tx] = v;
        size_t idx = (size_t)(b * LL + l) * DD + d0 + tx;
        g_q16[idx] = __float2half(v);
    }
    __syncthreads();
    size_t base = (size_t)b * DD * LL;
#pragma unroll
    for (int i = 0; i < 4; i++) {
        float v = tile[tx][ty + 8 * i];
        size_t idx = base + (size_t)(d0 + ty + 8 * i) * LL + l0 + tx;
        g_qT16[idx] = __float2half(v);
    }
}

// ---------------------------------------------------------------------------
// prep: bcat = [invw2 | -2c*invw2] fp16 single, cc[r] = sum c^2*invw2
// ---------------------------------------------------------------------------
__global__ void prep_kernel(const float* __restrict__ centers,
                            const float* __restrict__ widths) {
    int r = blockIdx.x;
    int t = threadIdx.x;  // 128
    float acc = 0.f;
    for (int d = t; d < DD; d += 128) {
        float w = widths[r * DD + d];
        float c = centers[r * DD + d];
        float iw = 1.0f / (w * w);
        float b2 = -2.0f * c * iw;
        g_bcat16[r * 1024 + d] = __float2half(iw);
        g_bcat16[r * 1024 + 512 + d] = __float2half(b2);
        acc += c * c * iw;
    }
    __shared__ float sred[128];
    sred[t] = acc;
    __syncthreads();
    for (int s = 64; s > 0; s >>= 1) {
        if (t < s) sred[t] += sred[t + s];
        __syncthreads();
    }
    if (t == 0) g_cc[r] = sred[0];
}

// ---------------------------------------------------------------------------
// rowsum: rinv[row] = 1 / sum_r e16[row][r]   (one warp per row)
// ---------------------------------------------------------------------------
__global__ void rowsum_kernel() {
    int row = blockIdx.x * 8 + (threadIdx.x >> 5);
    int lane = threadIdx.x & 31;
    const __half2* p = (const __half2*)(g_e16 + (size_t)row * RR);
    float s = 0.f;
#pragma unroll
    for (int i = 0; i < 8; i++) {
        float2 v = __half22float2(p[lane + 32 * i]);
        s += v.x + v.y;
    }
#pragma unroll
    for (int o = 16; o > 0; o >>= 1) s += __shfl_xor_sync(0xffffffffu, s, o);
    if (lane == 0) g_rinv[row] = 1.0f / s;
}

// ---------------------------------------------------------------------------
// fp16 1-pass NT GEMM via mma.sync m16n8k16 (A and B single fp16).
// 128x128 CTA tile, 8 warps of 64x32. K-chunk 64, 2-stage cp.async pipeline.
// 2 CTAs/SM. SMEM tile: 128 rows x 128B data, 144B pitch (conflict-free).
// MODE 0: qcat ((v+aux)^2 | (v+aux)) -> single fp16 (Chv; ldc=1024)
// MODE 1: e16 = exp(scale*(v+aux[n])) -> Chv (fp16; unnormalized softmax)
// MODE 2: fp16 single v+aux[n]  -> Chv
// MODE 4: fp32 v * rinv[bz*LL+m] -> Cf   (normalized attention output)
// ---------------------------------------------------------------------------
#define TPITCH 144
#define TILE_B (128 * TPITCH)        // 18432
#define STB (2 * TILE_B)             // A + B per stage
#define GEMM_SMEM (2 * STB)          // 73728

template <int MODE>
__global__ __launch_bounds__(256, 2) void gemm_s(
    const uint16_t* __restrict__ Ah, int lda, size_t sA,
    const uint16_t* __restrict__ Bh, int ldb, size_t sB,
    float* __restrict__ Cf, void* __restrict__ Chv,
    int ldc, size_t sC, const float* __restrict__ aux, int K) {
    extern __shared__ char smem[];
    uint32_t sb = smem_to_u32(smem);
    int t = threadIdx.x;
    int lane = t & 31, wid = t >> 5;
    int wm = wid & 1, wn = wid >> 1;
    int bn = blockIdx.x * 128, bm = blockIdx.y * 128;
    size_t bz = blockIdx.z;
    Ah += bz * sA;
    Bh += bz * sB;

    // cp.async plan: each thread covers rows r0+32i, one 16B column, per tile.
    int r0 = t >> 3;
    int cc = t & 7;
    const uint16_t* gA = Ah + (size_t)(bm + r0) * lda + cc * 8;
    const uint16_t* gB = Bh + (size_t)(bn + r0) * ldb + cc * 8;
    uint32_t soff = (uint32_t)(r0 * TPITCH + cc * 16);

    float acc[4][4][4] = {};
    const int nk = K >> 6;

    // prologue: chunk 0 -> stage 0
    {
#pragma unroll
        for (int i = 0; i < 4; i++) {
            uint32_t o = soff + (uint32_t)(i * 32 * TPITCH);
            CPASYNC16(sb + o,          gA + (size_t)(32 * i) * lda);
            CPASYNC16(sb + TILE_B + o, gB + (size_t)(32 * i) * ldb);
        }
        CPASYNC_COMMIT();
    }

    int lm = lane & 15, lq = lane >> 4;
    uint32_t a_base = (uint32_t)((wm * 64 + lm) * TPITCH);
    uint32_t b_base = (uint32_t)((wn * 32 + lm) * TPITCH);

    for (int kt = 0; kt < nk; kt++) {
        int buf = kt & 1;
        if (kt + 1 < nk) {
            uint32_t db = sb + (buf ^ 1) * STB;
            int koff = (kt + 1) * 64;
#pragma unroll
            for (int i = 0; i < 4; i++) {
                uint32_t o = soff + (uint32_t)(i * 32 * TPITCH);
                CPASYNC16(db + o,          gA + (size_t)(32 * i) * lda + koff);
                CPASYNC16(db + TILE_B + o, gB + (size_t)(32 * i) * ldb + koff);
            }
            CPASYNC_COMMIT();
            asm volatile("cp.async.wait_group 1;" ::: "memory");
        } else {
            asm volatile("cp.async.wait_group 0;" ::: "memory");
        }
        __syncthreads();
        uint32_t base = sb + buf * STB;
#pragma unroll
        for (int ks = 0; ks < 4; ks++) {
            uint32_t off16 = (uint32_t)((2 * ks + lq) * 16);
            uint32_t a[4][4], bb[4][2];
#pragma unroll
            for (int i = 0; i < 4; i++)
                LDSM4(a[i][0], a[i][1], a[i][2], a[i][3],
                      base + a_base + i * (16 * TPITCH) + off16);
#pragma unroll
            for (int jj = 0; jj < 2; jj++) {
                uint32_t q0, q1, q2, q3;
                LDSM4(q0, q1, q2, q3,
                      base + TILE_B + b_base + jj * (16 * TPITCH) + off16);
                bb[2 * jj][0] = q0; bb[2 * jj][1] = q2;
                bb[2 * jj + 1][0] = q1; bb[2 * jj + 1][1] = q3;
            }
#pragma unroll
            for (int i = 0; i < 4; i++)
#pragma unroll
                for (int j = 0; j < 4; j++) mma_hf(acc[i][j], a[i], bb[j]);
        }
        __syncthreads();
    }

    // epilogue (register-direct)
    int rbase = bm + wm * 64 + (lane >> 2);
    int nbase = bn + wn * 32 + (lane & 3) * 2;
#pragma unroll
    for (int i = 0; i < 4; i++) {
#pragma unroll
        for (int j = 0; j < 4; j++) {
            int n = nbase + j * 8;
#pragma unroll
            for (int h = 0; h < 2; h++) {
                int m = rbase + i * 16 + h * 8;
                float v0 = acc[i][j][2 * h];
                float v1 = acc[i][j][2 * h + 1];
                if (MODE == 0) {
                    __half* Cq = (__half*)Chv;
                    size_t crow = (size_t)m * ldc;
                    float q0 = v0 + aux[n], q1 = v1 + aux[n + 1];
                    __half2 s2; s2.x = __float2half(q0 * q0); s2.y = __float2half(q1 * q1);
                    *(__half2*)(Cq + crow + n) = s2;
                    __half2 qq; qq.x = __float2half(q0); qq.y = __float2half(q1);
                    *(__half2*)(Cq + crow + 512 + n) = qq;
                } else if (MODE == 1) {
                    const float scale = -0.5f / (float)DD;
                    __half* Ce = (__half*)Chv;
                    size_t crow = (size_t)m * ldc;
                    float e0 = __expf(scale * (v0 + aux[n]));
                    float e1 = __expf(scale * (v1 + aux[n + 1]));
                    __half2 ee; ee.x = __float2half(e0); ee.y = __float2half(e1);
                    *(__half2*)(Ce + crow + n) = ee;
                } else if (MODE == 2) {
                    __half* Ch = (__half*)Chv;
                    size_t crow = bz * sC + (size_t)m * ldc;
                    float q0 = v0 + aux[n], q1 = v1 + aux[n + 1];
                    __half2 hh; hh.x = __float2half(q0); hh.y = __float2half(q1);
                    *(__half2*)(Ch + crow + n) = hh;
                } else {
                    // MODE 4: multiply by per-row reciprocal softmax sum
                    float rv = aux[bz * LL + m];
                    size_t crow = bz * sC + (size_t)m * ldc;
                    float2 o; o.x = v0 * rv; o.y = v1 * rv;
                    *(float2*)(Cf + crow + n) = o;
                }
            }
        }
    }
}

// ---------------------------------------------------------------------------
extern "C" void kernel_launch(void* const* d_in, const int* in_sizes, int n_in,
                              void* d_out, int out_size) {
    const float* query   = (const float*)d_in[0];   // (B,L,D)
    const float* Wq      = (const float*)d_in[1];   // (D,D)
    const float* bq      = (const float*)d_in[2];   // (D,)
    const float* Wc      = (const float*)d_in[3];   // (R,L)
    const float* bc      = (const float*)d_in[4];   // (R,)
    const float* centers = (const float*)d_in[5];   // (R,D)
    const float* widths  = (const float*)d_in[6];   // (R,D)
    float* out = (float*)d_out;                     // (B,L,D)

    cudaFuncSetAttribute(gemm_s<0>, cudaFuncAttributeMaxDynamicSharedMemorySize, GEMM_SMEM);
    cudaFuncSetAttribute(gemm_s<1>, cudaFuncAttributeMaxDynamicSharedMemorySize, GEMM_SMEM);
    cudaFuncSetAttribute(gemm_s<2>, cudaFuncAttributeMaxDynamicSharedMemorySize, GEMM_SMEM);
    cudaFuncSetAttribute(gemm_s<4>, cudaFuncAttributeMaxDynamicSharedMemorySize, GEMM_SMEM);

    __half *q16, *wq16, *qcat16, *bcat16;
    __half *qT16, *wc16, *e16, *cq16;
    float *ccp, *rinv;
    cudaGetSymbolAddress((void**)&q16, g_q16);
    cudaGetSymbolAddress((void**)&wq16, g_wq16);
    cudaGetSymbolAddress((void**)&qcat16, g_qcat16);
    cudaGetSymbolAddress((void**)&bcat16, g_bcat16);
    cudaGetSymbolAddress((void**)&qT16, g_qT16);
    cudaGetSymbolAddress((void**)&wc16, g_wc16);
    cudaGetSymbolAddress((void**)&e16, g_e16);
    cudaGetSymbolAddress((void**)&cq16, g_cq16);
    cudaGetSymbolAddress((void**)&ccp, g_cc);
    cudaGetSymbolAddress((void**)&rinv, g_rinv);

    // prep: weight conversions + query dual-format + rule params
    {
        int n4 = (DD * DD) / 4;
        tofp16_kernel<<<(n4 + 255) / 256, 256>>>(Wq, wq16, n4);
        n4 = (RR * LL) / 4;
        tofp16_kernel<<<(n4 + 255) / 256, 256>>>(Wc, wc16, n4);
    }
    prep_kernel<<<RR, 128>>>(centers, widths);
    {
        dim3 g(LL / 32, DD / 32, BB);
        dim3 b(32, 8);
        query_prep_kernel<<<g, b>>>(query);
    }

    // G1 (fp16 1-pass): q = query @ Wq^T + bq -> qcat16 = [q^2 | q]
    {
        dim3 g(DD / 128, M1 / 128, 1);
        gemm_s<0><<<g, 256, GEMM_SMEM>>>(
            (const uint16_t*)q16, DD, 0,
            (const uint16_t*)wq16, DD, 0,
            nullptr, qcat16, 1024, 0, bq, DD);
    }
    // G2 (fp16 1-pass): e16 = exp(scale*(qcat16 @ bcat16^T + cc))  (K=1024)
    {
        dim3 g(RR / 128, M1 / 128, 1);
        gemm_s<1><<<g, 256, GEMM_SMEM>>>(
            (const uint16_t*)qcat16, 1024, 0,
            (const uint16_t*)bcat16, 1024, 0,
            nullptr, e16, RR, 0, ccp, 1024);
    }
    rowsum_kernel<<<M1 / 8, 256>>>();
    // G4 (fp16 1-pass): conqT[b] = qT[b] @ Wc^T + bc  (M=D, N=R, K=L)
    {
        dim3 g(RR / 128, DD / 128, BB);
        gemm_s<2><<<g, 256, GEMM_SMEM>>>(
            (const uint16_t*)qT16, LL, (size_t)DD * LL,
            (const uint16_t*)wc16, LL, 0,
            nullptr, cq16, RR, (size_t)DD * RR, bc, LL);
    }
    // G5 (fp16 1-pass): out[b] = (e[b] @ conqT[b]^T) * rinv  (M=L, N=D, K=R)
    {
        dim3 g(DD / 128, LL / 128, BB);
        gemm_s<4><<<g, 256, GEMM_SMEM>>>(
            (const uint16_t*)e16, RR, (size_t)LL * RR,
            (const uint16_t*)cq16, RR, (size_t)DD * RR,
            out, nullptr, DD, (size_t)LL * DD, rinv, RR);
    }
}